// round 2
// baseline (speedup 1.0000x reference)
#include <cuda_runtime.h>

// Problem constants
#define BATCH 8
#define SEQ   1024
#define CD    1024
#define NH    16
#define HD    64
#define MTOK  (BATCH * SEQ)      // 8192 tokens
#define NQKV  (3 * CD)           // 3072

// Scratch (no allocations allowed -> __device__ globals)
__device__ float g_qkv[MTOK * NQKV];   // [token, 3C]  (k | q | v)
__device__ float g_y[MTOK * CD];       // attention output [B,T,C]

// ---------------------------------------------------------------------------
// SGEMM: C[m,n] = sum_k A[m,k] * W[n,k]  (+ bias[n])      A:[M,K]  W:[N,K]
// 128x128 tile, BK=8, 256 threads, 8x8 per-thread microtile.
// ---------------------------------------------------------------------------
template <bool BIAS>
__global__ __launch_bounds__(256)
void sgemm_nt(const float* __restrict__ A, const float* __restrict__ W,
              const float* __restrict__ bias, float* __restrict__ C,
              int M, int N, int K)
{
    __shared__ float As[8][128];
    __shared__ float Bs[8][128];

    const int tid = threadIdx.x;
    const int tx = tid & 15;          // 0..15 -> n microtile
    const int ty = tid >> 4;          // 0..15 -> m microtile
    const int m0 = blockIdx.y * 128;
    const int n0 = blockIdx.x * 128;

    const int lrow = tid >> 1;        // 0..127
    const int lk   = (tid & 1) * 4;   // 0 or 4

    const float* Ap = A + (size_t)(m0 + lrow) * K + lk;
    const float* Wp = W + (size_t)(n0 + lrow) * K + lk;

    float acc[8][8];
#pragma unroll
    for (int i = 0; i < 8; i++)
#pragma unroll
        for (int j = 0; j < 8; j++) acc[i][j] = 0.0f;

    for (int k0 = 0; k0 < K; k0 += 8) {
        float4 va = *(const float4*)(Ap + k0);
        float4 vb = *(const float4*)(Wp + k0);
        As[lk + 0][lrow] = va.x; As[lk + 1][lrow] = va.y;
        As[lk + 2][lrow] = va.z; As[lk + 3][lrow] = va.w;
        Bs[lk + 0][lrow] = vb.x; Bs[lk + 1][lrow] = vb.y;
        Bs[lk + 2][lrow] = vb.z; Bs[lk + 3][lrow] = vb.w;
        __syncthreads();

#pragma unroll
        for (int kk = 0; kk < 8; kk++) {
            float4 a0 = *(const float4*)&As[kk][ty * 8];
            float4 a1 = *(const float4*)&As[kk][ty * 8 + 4];
            float4 b0 = *(const float4*)&Bs[kk][tx * 8];
            float4 b1 = *(const float4*)&Bs[kk][tx * 8 + 4];
            float ar[8] = {a0.x, a0.y, a0.z, a0.w, a1.x, a1.y, a1.z, a1.w};
            float br[8] = {b0.x, b0.y, b0.z, b0.w, b1.x, b1.y, b1.z, b1.w};
#pragma unroll
            for (int i = 0; i < 8; i++)
#pragma unroll
                for (int j = 0; j < 8; j++)
                    acc[i][j] = fmaf(ar[i], br[j], acc[i][j]);
        }
        __syncthreads();
    }

    float bn[8];
    if (BIAS) {
#pragma unroll
        for (int j = 0; j < 8; j++) bn[j] = bias[n0 + tx * 8 + j];
    }
#pragma unroll
    for (int i = 0; i < 8; i++) {
        size_t row = (size_t)(m0 + ty * 8 + i) * N + n0 + tx * 8;
        float4 o0, o1;
        if (BIAS) {
            o0 = make_float4(acc[i][0] + bn[0], acc[i][1] + bn[1],
                             acc[i][2] + bn[2], acc[i][3] + bn[3]);
            o1 = make_float4(acc[i][4] + bn[4], acc[i][5] + bn[5],
                             acc[i][6] + bn[6], acc[i][7] + bn[7]);
        } else {
            o0 = make_float4(acc[i][0], acc[i][1], acc[i][2], acc[i][3]);
            o1 = make_float4(acc[i][4], acc[i][5], acc[i][6], acc[i][7]);
        }
        *(float4*)&C[row]     = o0;
        *(float4*)&C[row + 4] = o1;
    }
}

// ---------------------------------------------------------------------------
// Flash attention (fp32, online softmax), 64x64 tiles, causal.
// qkv layout per token row (stride 3072): [k(1024) | q(1024) | v(1024)],
// head h occupies cols h*64..h*64+63 inside each part.
// Block: 256 threads handles one (b, h, q-tile of 64 rows).
// ---------------------------------------------------------------------------
#define PAD 68
#define ATTN_SMEM_FLOATS (4 * 64 * PAD + 3 * 64)
#define ATTN_SMEM_BYTES  (ATTN_SMEM_FLOATS * 4)

__global__ __launch_bounds__(256)
void attn_kernel(const float* __restrict__ qkv, float* __restrict__ y)
{
    extern __shared__ float sm[];
    float* QsT   = sm;                    // [d=64][row 64] stride PAD (d-major)
    float* KsT   = QsT + 64 * PAD;        // [d=64][row 64]
    float* Vs    = KsT + 64 * PAD;        // [row 64][d 64]
    float* Ss    = Vs  + 64 * PAD;        // [qrow 64][krow 64]   (scores -> probs)
    float* row_m = Ss  + 64 * PAD;        // [64]
    float* row_l = row_m + 64;            // [64]
    float* row_c = row_l + 64;            // [64]

    const int tid = threadIdx.x;
    const int qt = blockIdx.x;            // q tile index (0..15)
    const int h  = blockIdx.y;
    const int b  = blockIdx.z;
    const int q0 = qt * 64;

    const int koff = h * HD;
    const int qoff = CD + h * HD;
    const int voff = 2 * CD + h * HD;
    const int tok0 = b * SEQ;

    const int lrow = tid >> 2;            // 0..63 (loader row)
    const int lg   = tid & 3;             // 0..3  (loader 16-col group)

    // Load Q tile (d-major transpose into smem)
    {
        const float* src = qkv + (size_t)(tok0 + q0 + lrow) * NQKV + qoff + lg * 16;
#pragma unroll
        for (int v4 = 0; v4 < 4; v4++) {
            float4 q4 = *(const float4*)(src + v4 * 4);
            int d = lg * 16 + v4 * 4;
            QsT[(d + 0) * PAD + lrow] = q4.x;
            QsT[(d + 1) * PAD + lrow] = q4.y;
            QsT[(d + 2) * PAD + lrow] = q4.z;
            QsT[(d + 3) * PAD + lrow] = q4.w;
        }
    }
    if (tid < 64) { row_m[tid] = -1e30f; row_l[tid] = 0.0f; }

    const int ia = tid >> 4;              // 0..15 : owns q rows ia*4..ia*4+3
    const int ja = tid & 15;              // 0..15 : owns k cols / d cols ja*4..ja*4+3
    const int pi = tid >> 2;              // 0..63 : softmax row
    const int pg = tid & 3;               // 0..3  : softmax 16-col chunk
    const float scale = 0.125f;           // 1/sqrt(64)

    float acc[4][4];
#pragma unroll
    for (int r = 0; r < 4; r++)
#pragma unroll
        for (int c = 0; c < 4; c++) acc[r][c] = 0.0f;

    for (int kt = 0; kt <= qt; kt++) {
        const int k0 = kt * 64;
        __syncthreads();  // previous iter done (also orders Q load / init)

        // Load K (d-major) and V (row-major) tiles
        {
            const float* ks = qkv + (size_t)(tok0 + k0 + lrow) * NQKV + koff + lg * 16;
            const float* vs = qkv + (size_t)(tok0 + k0 + lrow) * NQKV + voff + lg * 16;
#pragma unroll
            for (int v4 = 0; v4 < 4; v4++) {
                float4 k4 = *(const float4*)(ks + v4 * 4);
                int d = lg * 16 + v4 * 4;
                KsT[(d + 0) * PAD + lrow] = k4.x;
                KsT[(d + 1) * PAD + lrow] = k4.y;
                KsT[(d + 2) * PAD + lrow] = k4.z;
                KsT[(d + 3) * PAD + lrow] = k4.w;
            }
#pragma unroll
            for (int v4 = 0; v4 < 4; v4++) {
                float4 vv = *(const float4*)(vs + v4 * 4);
                *(float4*)&Vs[lrow * PAD + lg * 16 + v4 * 4] = vv;
            }
        }
        __syncthreads();

        // Phase A: S[4x4] = Q Kt  (then scale + causal mask) -> Ss
        {
            float s[4][4];
#pragma unroll
            for (int r = 0; r < 4; r++)
#pragma unroll
                for (int c = 0; c < 4; c++) s[r][c] = 0.0f;

#pragma unroll 8
            for (int d = 0; d < 64; d++) {
                float4 qv = *(const float4*)&QsT[d * PAD + ia * 4];
                float4 kv = *(const float4*)&KsT[d * PAD + ja * 4];
                float qr[4] = {qv.x, qv.y, qv.z, qv.w};
                float kr[4] = {kv.x, kv.y, kv.z, kv.w};
#pragma unroll
                for (int r = 0; r < 4; r++)
#pragma unroll
                    for (int c = 0; c < 4; c++)
                        s[r][c] = fmaf(qr[r], kr[c], s[r][c]);
            }
            const bool diag = (kt == qt);
#pragma unroll
            for (int r = 0; r < 4; r++) {
                int i = ia * 4 + r;
                float tmpv[4];
#pragma unroll
                for (int c = 0; c < 4; c++) {
                    int j = ja * 4 + c;
                    tmpv[c] = (diag && j > i) ? -1e30f : s[r][c] * scale;
                }
                *(float4*)&Ss[i * PAD + ja * 4] = *(float4*)tmpv;
            }
        }
        __syncthreads();

        // Phase B: online softmax over this tile's 64 columns
        {
            float* srow = Ss + pi * PAD + pg * 16;
            float pv[16];
            float tmax = -1e30f;
#pragma unroll
            for (int jj = 0; jj < 16; jj++) {
                pv[jj] = srow[jj];
                tmax = fmaxf(tmax, pv[jj]);
            }
            tmax = fmaxf(tmax, __shfl_xor_sync(0xffffffffu, tmax, 1));
            tmax = fmaxf(tmax, __shfl_xor_sync(0xffffffffu, tmax, 2));
            float m_old = row_m[pi];
            float m_new = fmaxf(m_old, tmax);
            float lsum = 0.0f;
#pragma unroll
            for (int jj = 0; jj < 16; jj++) {
                float e = __expf(pv[jj] - m_new);
                srow[jj] = e;
                lsum += e;
            }
            lsum += __shfl_xor_sync(0xffffffffu, lsum, 1);
            lsum += __shfl_xor_sync(0xffffffffu, lsum, 2);
            if (pg == 0) {
                float cc = __expf(m_old - m_new);
                row_c[pi] = cc;
                row_l[pi] = row_l[pi] * cc + lsum;
                row_m[pi] = m_new;
            }
        }
        __syncthreads();

        // Phase C: acc = acc * c_row + P @ V   (thread owns rows ia*4.., dims ja*4..)
        {
#pragma unroll
            for (int r = 0; r < 4; r++) {
                float cr = row_c[ia * 4 + r];
#pragma unroll
                for (int c = 0; c < 4; c++) acc[r][c] *= cr;
            }
#pragma unroll 8
            for (int j = 0; j < 64; j++) {
                float4 vv = *(const float4*)&Vs[j * PAD + ja * 4];
                float p0 = Ss[(ia * 4 + 0) * PAD + j];
                float p1 = Ss[(ia * 4 + 1) * PAD + j];
                float p2 = Ss[(ia * 4 + 2) * PAD + j];
                float p3 = Ss[(ia * 4 + 3) * PAD + j];
                acc[0][0] = fmaf(p0, vv.x, acc[0][0]);
                acc[0][1] = fmaf(p0, vv.y, acc[0][1]);
                acc[0][2] = fmaf(p0, vv.z, acc[0][2]);
                acc[0][3] = fmaf(p0, vv.w, acc[0][3]);
                acc[1][0] = fmaf(p1, vv.x, acc[1][0]);
                acc[1][1] = fmaf(p1, vv.y, acc[1][1]);
                acc[1][2] = fmaf(p1, vv.z, acc[1][2]);
                acc[1][3] = fmaf(p1, vv.w, acc[1][3]);
                acc[2][0] = fmaf(p2, vv.x, acc[2][0]);
                acc[2][1] = fmaf(p2, vv.y, acc[2][1]);
                acc[2][2] = fmaf(p2, vv.z, acc[2][2]);
                acc[2][3] = fmaf(p2, vv.w, acc[2][3]);
                acc[3][0] = fmaf(p3, vv.x, acc[3][0]);
                acc[3][1] = fmaf(p3, vv.y, acc[3][1]);
                acc[3][2] = fmaf(p3, vv.z, acc[3][2]);
                acc[3][3] = fmaf(p3, vv.w, acc[3][3]);
            }
        }
    }

    // Final: divide by l and write y[b, t, h*64 + d]
#pragma unroll
    for (int r = 0; r < 4; r++) {
        int i = ia * 4 + r;
        float inv = 1.0f / row_l[i];
        float4 o = make_float4(acc[r][0] * inv, acc[r][1] * inv,
                               acc[r][2] * inv, acc[r][3] * inv);
        *(float4*)&y[(size_t)(tok0 + q0 + i) * CD + h * HD + ja * 4] = o;
    }
}

// ---------------------------------------------------------------------------
extern "C" void kernel_launch(void* const* d_in, const int* in_sizes, int n_in,
                              void* d_out, int out_size)
{
    const float* x      = (const float*)d_in[0];
    const float* w_attn = (const float*)d_in[1];
    const float* w_proj = (const float*)d_in[2];
    const float* b_proj = (const float*)d_in[3];
    float* out = (float*)d_out;

    float *qkv, *y;
    cudaGetSymbolAddress((void**)&qkv, g_qkv);
    cudaGetSymbolAddress((void**)&y, g_y);

    cudaFuncSetAttribute(attn_kernel,
                         cudaFuncAttributeMaxDynamicSharedMemorySize,
                         ATTN_SMEM_BYTES);

    // 1) fused QKV projection: qkv = x @ w_attn^T
    sgemm_nt<false><<<dim3(NQKV / 128, MTOK / 128), 256>>>(
        x, w_attn, nullptr, qkv, MTOK, NQKV, CD);

    // 2) causal flash attention -> y [B,T,C]
    attn_kernel<<<dim3(SEQ / 64, NH, BATCH), 256, ATTN_SMEM_BYTES>>>(qkv, y);

    // 3) output projection: out = y @ w_proj^T + b_proj
    sgemm_nt<true><<<dim3(CD / 128, MTOK / 128), 256>>>(
        y, w_proj, b_proj, out, MTOK, CD, CD);
}

// round 4
// speedup vs baseline: 1.5732x; 1.5732x over previous
#include <cuda_runtime.h>
#include <cuda_bf16.h>
#include <cstdint>

// Problem constants
#define BATCH 8
#define SEQ   1024
#define CD    1024
#define NH    16
#define HD    64
#define MTOK  (BATCH * SEQ)      // 8192 tokens
#define NQKV  (3 * CD)           // 3072

// Scratch (no allocations allowed -> __device__ globals)
__device__ float g_qkv[MTOK * NQKV];              // [token, 3C]  (k | q | v)
__device__ float g_y[MTOK * CD];                  // attention output [B,T,C]
__device__ __nv_bfloat16 g_xhi[MTOK * CD],  g_xlo[MTOK * CD];
__device__ __nv_bfloat16 g_wahi[NQKV * CD], g_walo[NQKV * CD];
__device__ __nv_bfloat16 g_wphi[CD * CD],   g_wplo[CD * CD];
__device__ __nv_bfloat16 g_yhi[MTOK * CD],  g_ylo[MTOK * CD];

// ---------------------------------------------------------------------------
// PTX helpers (portable sm_80+ tensor path: cp.async + ldmatrix + mma.sync)
// ---------------------------------------------------------------------------
__device__ __forceinline__ uint32_t smem_u32(const void* p) {
    return (uint32_t)__cvta_generic_to_shared(p);
}
__device__ __forceinline__ void cp16(uint32_t dst_smem, const void* src) {
    asm volatile("cp.async.cg.shared.global [%0], [%1], 16;"
                 :: "r"(dst_smem), "l"(__cvta_generic_to_global(src)) : "memory");
}
__device__ __forceinline__ void ldsm4(uint32_t* r, uint32_t addr) {
    asm volatile("ldmatrix.sync.aligned.m8n8.x4.shared.b16 {%0,%1,%2,%3}, [%4];"
                 : "=r"(r[0]), "=r"(r[1]), "=r"(r[2]), "=r"(r[3]) : "r"(addr));
}
__device__ __forceinline__ void mma16816(float* d, const uint32_t* a,
                                         uint32_t b0, uint32_t b1) {
    asm volatile(
        "mma.sync.aligned.m16n8k16.row.col.f32.bf16.bf16.f32 "
        "{%0,%1,%2,%3}, {%4,%5,%6,%7}, {%8,%9}, {%0,%1,%2,%3};"
        : "+f"(d[0]), "+f"(d[1]), "+f"(d[2]), "+f"(d[3])
        : "r"(a[0]), "r"(a[1]), "r"(a[2]), "r"(a[3]), "r"(b0), "r"(b1));
}

// ---------------------------------------------------------------------------
// fp32 -> (bf16 hi, bf16 lo) split, 4 elements per thread
// ---------------------------------------------------------------------------
__global__ __launch_bounds__(256)
void split_bf16(const float* __restrict__ in, __nv_bfloat16* __restrict__ hi,
                __nv_bfloat16* __restrict__ lo, int n)
{
    int i = (blockIdx.x * blockDim.x + threadIdx.x) * 4;
    if (i >= n) return;
    float4 v = *(const float4*)(in + i);
    __nv_bfloat16 h0 = __float2bfloat16_rn(v.x);
    __nv_bfloat16 h1 = __float2bfloat16_rn(v.y);
    __nv_bfloat16 h2 = __float2bfloat16_rn(v.z);
    __nv_bfloat16 h3 = __float2bfloat16_rn(v.w);
    __nv_bfloat162 hp0; hp0.x = h0; hp0.y = h1;
    __nv_bfloat162 hp1; hp1.x = h2; hp1.y = h3;
    __nv_bfloat162 lp0, lp1;
    lp0.x = __float2bfloat16_rn(v.x - __bfloat162float(h0));
    lp0.y = __float2bfloat16_rn(v.y - __bfloat162float(h1));
    lp1.x = __float2bfloat16_rn(v.z - __bfloat162float(h2));
    lp1.y = __float2bfloat16_rn(v.w - __bfloat162float(h3));
    *(__nv_bfloat162*)(hi + i)     = hp0;
    *(__nv_bfloat162*)(hi + i + 2) = hp1;
    *(__nv_bfloat162*)(lo + i)     = lp0;
    *(__nv_bfloat162*)(lo + i + 2) = lp1;
}

// ---------------------------------------------------------------------------
// mma.sync GEMM with bf16 error-compensated split (3 MMA terms):
//   C[m,n] = sum_k (Ah+Al)[m,k] * (Bh+Bl)[n,k]   (Al*Bl term dropped, ~4e-6)
// 128x128 CTA tile, 8 warps (each 32m x 64n), BK=32, 3-stage cp.async pipe.
// smem per stage: Ah | Al | Bh | Bl, each 128 rows x 64B, XOR-swizzled.
// ---------------------------------------------------------------------------
#define BK 32
#define TEN_BYTES  8192                 // one tensor tile: 128 * 64B
#define STAGE_BYTES (4 * TEN_BYTES)     // 32 KB
#define NSTAGE 3
#define GEMM_SMEM (NSTAGE * STAGE_BYTES)  // 96 KB

// physical byte offset of (row r, 16B-chunk ch) inside one tensor tile
__device__ __forceinline__ uint32_t sw(uint32_t r, uint32_t ch) {
    return r * 64u + (((ch) ^ (r & 3u)) << 4);
}

template <bool BIAS>
__global__ __launch_bounds__(256)
void gemm_bf16x3(const __nv_bfloat16* __restrict__ Ah, const __nv_bfloat16* __restrict__ Al,
                 const __nv_bfloat16* __restrict__ Bh, const __nv_bfloat16* __restrict__ Bl,
                 const float* __restrict__ bias, float* __restrict__ C,
                 int M, int N, int K)
{
    extern __shared__ char smem[];
    const uint32_t sb = smem_u32(smem);
    const int tid = threadIdx.x;
    const int wid = tid >> 5, l = tid & 31;
    const int m0 = blockIdx.y * 128, n0 = blockIdx.x * 128;
    const int NCH = K >> 5;            // BK=32

    // ---- loader mapping: 4 groups of 64 threads, one tensor each;
    //      each thread loads 2 rows x 4 chunks (64B contiguous per row)
    const int lt = tid >> 6;           // tensor 0..3: Ah, Al, Bh, Bl
    const int lu = tid & 63;
    const __nv_bfloat16* gbase =
        (lt == 0) ? Ah + (size_t)m0 * K :
        (lt == 1) ? Al + (size_t)m0 * K :
        (lt == 2) ? Bh + (size_t)n0 * K :
                    Bl + (size_t)n0 * K;

    auto load_chunk = [&](int c) {
        const uint32_t stage = sb + (uint32_t)(c % NSTAGE) * STAGE_BYTES + lt * TEN_BYTES;
        const int k0 = c << 5;
#pragma unroll
        for (int rr = 0; rr < 2; rr++) {
            const int r = lu * 2 + rr;
            const __nv_bfloat16* gp = gbase + (size_t)r * K + k0;
#pragma unroll
            for (int ch = 0; ch < 4; ch++)
                cp16(stage + sw(r, ch), gp + ch * 8);
        }
        asm volatile("cp.async.commit_group;" ::: "memory");
    };

    // ---- warp tile: wm in 0..3 (rows wm*32), wn in 0..1 (cols wn*64)
    const int wm = wid >> 1, wn = wid & 1;

    // fragment smem offsets (within a tensor tile), constant across chunks
    uint32_t offA[2][2], offB[4][2];
#pragma unroll
    for (int i = 0; i < 2; i++) {
        uint32_t r = wm * 32 + i * 16 + (l & 15);
#pragma unroll
        for (int s = 0; s < 2; s++)
            offA[i][s] = sw(r, s * 2 + (l >> 4));
    }
#pragma unroll
    for (int p = 0; p < 4; p++) {
        uint32_t r = wn * 64 + p * 16 + (l & 7) + ((l >> 4) << 3);
#pragma unroll
        for (int s = 0; s < 2; s++)
            offB[p][s] = sw(r, s * 2 + ((l >> 3) & 1));
    }

    float acc[2][8][4];
#pragma unroll
    for (int i = 0; i < 2; i++)
#pragma unroll
        for (int j = 0; j < 8; j++)
#pragma unroll
            for (int q = 0; q < 4; q++) acc[i][j][q] = 0.0f;

    load_chunk(0);
    load_chunk(1);

    for (int c = 0; c < NCH; c++) {
        if (c + 2 < NCH) {
            load_chunk(c + 2);
            asm volatile("cp.async.wait_group 2;" ::: "memory");
        } else if (c + 1 < NCH) {
            asm volatile("cp.async.wait_group 1;" ::: "memory");
        } else {
            asm volatile("cp.async.wait_group 0;" ::: "memory");
        }
        __syncthreads();

        const uint32_t stage = sb + (uint32_t)(c % NSTAGE) * STAGE_BYTES;
#pragma unroll
        for (int s = 0; s < 2; s++) {
            uint32_t ah[2][4], al2[2][4];
#pragma unroll
            for (int i = 0; i < 2; i++) {
                ldsm4(ah[i],  stage + offA[i][s]);
                ldsm4(al2[i], stage + TEN_BYTES + offA[i][s]);
            }
            uint32_t bh[4][4], bl[4][4];
#pragma unroll
            for (int p = 0; p < 4; p++) {
                ldsm4(bh[p], stage + 2 * TEN_BYTES + offB[p][s]);
                ldsm4(bl[p], stage + 3 * TEN_BYTES + offB[p][s]);
            }
#pragma unroll
            for (int i = 0; i < 2; i++)
#pragma unroll
                for (int j = 0; j < 8; j++) {
                    const int p = j >> 1, h = (j & 1) * 2;
                    mma16816(acc[i][j], ah[i],  bh[p][h], bh[p][h + 1]);
                    mma16816(acc[i][j], ah[i],  bl[p][h], bl[p][h + 1]);
                    mma16816(acc[i][j], al2[i], bh[p][h], bh[p][h + 1]);
                }
        }
        __syncthreads();
    }

    // ---- epilogue: c frag lane mapping: rows l>>2 (+8), cols (l&3)*2
    const int rowq = l >> 2, colq = (l & 3) * 2;
#pragma unroll
    for (int j = 0; j < 8; j++) {
        const int ccol = n0 + wn * 64 + j * 8 + colq;
        float b0 = 0.f, b1 = 0.f;
        if (BIAS) { b0 = bias[ccol]; b1 = bias[ccol + 1]; }
#pragma unroll
        for (int i = 0; i < 2; i++) {
            const int r = m0 + wm * 32 + i * 16 + rowq;
            float2 v0 = make_float2(acc[i][j][0] + b0, acc[i][j][1] + b1);
            float2 v1 = make_float2(acc[i][j][2] + b0, acc[i][j][3] + b1);
            *(float2*)&C[(size_t)r * N + ccol]       = v0;
            *(float2*)&C[(size_t)(r + 8) * N + ccol] = v1;
        }
    }
}

// ---------------------------------------------------------------------------
// Flash attention (fp32, online softmax), 64x64 tiles, causal. (unchanged)
// ---------------------------------------------------------------------------
#define PAD 68
#define ATTN_SMEM_FLOATS (4 * 64 * PAD + 3 * 64)
#define ATTN_SMEM_BYTES  (ATTN_SMEM_FLOATS * 4)

__global__ __launch_bounds__(256)
void attn_kernel(const float* __restrict__ qkv, float* __restrict__ y)
{
    extern __shared__ float sm[];
    float* QsT   = sm;
    float* KsT   = QsT + 64 * PAD;
    float* Vs    = KsT + 64 * PAD;
    float* Ss    = Vs  + 64 * PAD;
    float* row_m = Ss  + 64 * PAD;
    float* row_l = row_m + 64;
    float* row_c = row_l + 64;

    const int tid = threadIdx.x;
    const int qt = blockIdx.x;
    const int h  = blockIdx.y;
    const int b  = blockIdx.z;
    const int q0 = qt * 64;

    const int koff = h * HD;
    const int qoff = CD + h * HD;
    const int voff = 2 * CD + h * HD;
    const int tok0 = b * SEQ;

    const int lrow = tid >> 2;
    const int lg   = tid & 3;

    {
        const float* src = qkv + (size_t)(tok0 + q0 + lrow) * NQKV + qoff + lg * 16;
#pragma unroll
        for (int v4 = 0; v4 < 4; v4++) {
            float4 q4 = *(const float4*)(src + v4 * 4);
            int d = lg * 16 + v4 * 4;
            QsT[(d + 0) * PAD + lrow] = q4.x;
            QsT[(d + 1) * PAD + lrow] = q4.y;
            QsT[(d + 2) * PAD + lrow] = q4.z;
            QsT[(d + 3) * PAD + lrow] = q4.w;
        }
    }
    if (tid < 64) { row_m[tid] = -1e30f; row_l[tid] = 0.0f; }

    const int ia = tid >> 4;
    const int ja = tid & 15;
    const int pi = tid >> 2;
    const int pg = tid & 3;
    const float scale = 0.125f;

    float acc[4][4];
#pragma unroll
    for (int r = 0; r < 4; r++)
#pragma unroll
        for (int c = 0; c < 4; c++) acc[r][c] = 0.0f;

    for (int kt = 0; kt <= qt; kt++) {
        const int k0 = kt * 64;
        __syncthreads();

        {
            const float* ks = qkv + (size_t)(tok0 + k0 + lrow) * NQKV + koff + lg * 16;
            const float* vs = qkv + (size_t)(tok0 + k0 + lrow) * NQKV + voff + lg * 16;
#pragma unroll
            for (int v4 = 0; v4 < 4; v4++) {
                float4 k4 = *(const float4*)(ks + v4 * 4);
                int d = lg * 16 + v4 * 4;
                KsT[(d + 0) * PAD + lrow] = k4.x;
                KsT[(d + 1) * PAD + lrow] = k4.y;
                KsT[(d + 2) * PAD + lrow] = k4.z;
                KsT[(d + 3) * PAD + lrow] = k4.w;
            }
#pragma unroll
            for (int v4 = 0; v4 < 4; v4++) {
                float4 vv = *(const float4*)(vs + v4 * 4);
                *(float4*)&Vs[lrow * PAD + lg * 16 + v4 * 4] = vv;
            }
        }
        __syncthreads();

        {
            float s[4][4];
#pragma unroll
            for (int r = 0; r < 4; r++)
#pragma unroll
                for (int c = 0; c < 4; c++) s[r][c] = 0.0f;

#pragma unroll 8
            for (int d = 0; d < 64; d++) {
                float4 qv = *(const float4*)&QsT[d * PAD + ia * 4];
                float4 kv = *(const float4*)&KsT[d * PAD + ja * 4];
                float qr[4] = {qv.x, qv.y, qv.z, qv.w};
                float kr[4] = {kv.x, kv.y, kv.z, kv.w};
#pragma unroll
                for (int r = 0; r < 4; r++)
#pragma unroll
                    for (int c = 0; c < 4; c++)
                        s[r][c] = fmaf(qr[r], kr[c], s[r][c]);
            }
            const bool diag = (kt == qt);
#pragma unroll
            for (int r = 0; r < 4; r++) {
                int i = ia * 4 + r;
                float tmpv[4];
#pragma unroll
                for (int c = 0; c < 4; c++) {
                    int j = ja * 4 + c;
                    tmpv[c] = (diag && j > i) ? -1e30f : s[r][c] * scale;
                }
                *(float4*)&Ss[i * PAD + ja * 4] = *(float4*)tmpv;
            }
        }
        __syncthreads();

        {
            float* srow = Ss + pi * PAD + pg * 16;
            float pv[16];
            float tmax = -1e30f;
#pragma unroll
            for (int jj = 0; jj < 16; jj++) {
                pv[jj] = srow[jj];
                tmax = fmaxf(tmax, pv[jj]);
            }
            tmax = fmaxf(tmax, __shfl_xor_sync(0xffffffffu, tmax, 1));
            tmax = fmaxf(tmax, __shfl_xor_sync(0xffffffffu, tmax, 2));
            float m_old = row_m[pi];
            float m_new = fmaxf(m_old, tmax);
            float lsum = 0.0f;
#pragma unroll
            for (int jj = 0; jj < 16; jj++) {
                float e = __expf(pv[jj] - m_new);
                srow[jj] = e;
                lsum += e;
            }
            lsum += __shfl_xor_sync(0xffffffffu, lsum, 1);
            lsum += __shfl_xor_sync(0xffffffffu, lsum, 2);
            if (pg == 0) {
                float cc = __expf(m_old - m_new);
                row_c[pi] = cc;
                row_l[pi] = row_l[pi] * cc + lsum;
                row_m[pi] = m_new;
            }
        }
        __syncthreads();

        {
#pragma unroll
            for (int r = 0; r < 4; r++) {
                float cr = row_c[ia * 4 + r];
#pragma unroll
                for (int c = 0; c < 4; c++) acc[r][c] *= cr;
            }
#pragma unroll 8
            for (int j = 0; j < 64; j++) {
                float4 vv = *(const float4*)&Vs[j * PAD + ja * 4];
                float p0 = Ss[(ia * 4 + 0) * PAD + j];
                float p1 = Ss[(ia * 4 + 1) * PAD + j];
                float p2 = Ss[(ia * 4 + 2) * PAD + j];
                float p3 = Ss[(ia * 4 + 3) * PAD + j];
                acc[0][0] = fmaf(p0, vv.x, acc[0][0]);
                acc[0][1] = fmaf(p0, vv.y, acc[0][1]);
                acc[0][2] = fmaf(p0, vv.z, acc[0][2]);
                acc[0][3] = fmaf(p0, vv.w, acc[0][3]);
                acc[1][0] = fmaf(p1, vv.x, acc[1][0]);
                acc[1][1] = fmaf(p1, vv.y, acc[1][1]);
                acc[1][2] = fmaf(p1, vv.z, acc[1][2]);
                acc[1][3] = fmaf(p1, vv.w, acc[1][3]);
                acc[2][0] = fmaf(p2, vv.x, acc[2][0]);
                acc[2][1] = fmaf(p2, vv.y, acc[2][1]);
                acc[2][2] = fmaf(p2, vv.z, acc[2][2]);
                acc[2][3] = fmaf(p2, vv.w, acc[2][3]);
                acc[3][0] = fmaf(p3, vv.x, acc[3][0]);
                acc[3][1] = fmaf(p3, vv.y, acc[3][1]);
                acc[3][2] = fmaf(p3, vv.z, acc[3][2]);
                acc[3][3] = fmaf(p3, vv.w, acc[3][3]);
            }
        }
    }

#pragma unroll
    for (int r = 0; r < 4; r++) {
        int i = ia * 4 + r;
        float inv = 1.0f / row_l[i];
        float4 o = make_float4(acc[r][0] * inv, acc[r][1] * inv,
                               acc[r][2] * inv, acc[r][3] * inv);
        *(float4*)&y[(size_t)(tok0 + q0 + i) * CD + h * HD + ja * 4] = o;
    }
}

// ---------------------------------------------------------------------------
extern "C" void kernel_launch(void* const* d_in, const int* in_sizes, int n_in,
                              void* d_out, int out_size)
{
    const float* x      = (const float*)d_in[0];
    const float* w_attn = (const float*)d_in[1];
    const float* w_proj = (const float*)d_in[2];
    const float* b_proj = (const float*)d_in[3];
    float* out = (float*)d_out;

    float *qkv, *y;
    __nv_bfloat16 *xhi, *xlo, *wahi, *walo, *wphi, *wplo, *yhi, *ylo;
    cudaGetSymbolAddress((void**)&qkv,  g_qkv);
    cudaGetSymbolAddress((void**)&y,    g_y);
    cudaGetSymbolAddress((void**)&xhi,  g_xhi);
    cudaGetSymbolAddress((void**)&xlo,  g_xlo);
    cudaGetSymbolAddress((void**)&wahi, g_wahi);
    cudaGetSymbolAddress((void**)&walo, g_walo);
    cudaGetSymbolAddress((void**)&wphi, g_wphi);
    cudaGetSymbolAddress((void**)&wplo, g_wplo);
    cudaGetSymbolAddress((void**)&yhi,  g_yhi);
    cudaGetSymbolAddress((void**)&ylo,  g_ylo);

    cudaFuncSetAttribute(attn_kernel,
                         cudaFuncAttributeMaxDynamicSharedMemorySize, ATTN_SMEM_BYTES);
    cudaFuncSetAttribute(gemm_bf16x3<false>,
                         cudaFuncAttributeMaxDynamicSharedMemorySize, GEMM_SMEM);
    cudaFuncSetAttribute(gemm_bf16x3<true>,
                         cudaFuncAttributeMaxDynamicSharedMemorySize, GEMM_SMEM);

    // 0) split inputs into bf16 hi/lo
    split_bf16<<<(MTOK * CD / 4 + 255) / 256, 256>>>(x, xhi, xlo, MTOK * CD);
    split_bf16<<<(NQKV * CD / 4 + 255) / 256, 256>>>(w_attn, wahi, walo, NQKV * CD);
    split_bf16<<<(CD * CD / 4 + 255) / 256, 256>>>(w_proj, wphi, wplo, CD * CD);

    // 1) fused QKV projection: qkv = x @ w_attn^T   (mma.sync bf16 x3)
    gemm_bf16x3<false><<<dim3(NQKV / 128, MTOK / 128), 256, GEMM_SMEM>>>(
        xhi, xlo, wahi, walo, nullptr, qkv, MTOK, NQKV, CD);

    // 2) causal flash attention -> y [B,T,C]
    attn_kernel<<<dim3(SEQ / 64, NH, BATCH), 256, ATTN_SMEM_BYTES>>>(qkv, y);

    // 3) split y, then output projection: out = y @ w_proj^T + b_proj
    split_bf16<<<(MTOK * CD / 4 + 255) / 256, 256>>>(y, yhi, ylo, MTOK * CD);
    gemm_bf16x3<true><<<dim3(CD / 128, MTOK / 128), 256, GEMM_SMEM>>>(
        yhi, ylo, wphi, wplo, b_proj, out, MTOK, CD, CD);
}

// round 5
// speedup vs baseline: 2.1231x; 1.3496x over previous
#include <cuda_runtime.h>
#include <cuda_bf16.h>
#include <cstdint>

// Problem constants
#define BATCH 8
#define SEQ   1024
#define CD    1024
#define NH    16
#define HD    64
#define MTOK  (BATCH * SEQ)      // 8192 tokens
#define NQKV  (3 * CD)           // 3072

// Scratch (no allocations allowed -> __device__ globals)
__device__ __nv_bfloat16 g_xhi[MTOK * CD],  g_xlo[MTOK * CD];
__device__ __nv_bfloat16 g_wahi[NQKV * CD], g_walo[NQKV * CD];
__device__ __nv_bfloat16 g_wphi[CD * CD],   g_wplo[CD * CD];
__device__ __nv_bfloat16 g_qkvhi[MTOK * NQKV], g_qkvlo[MTOK * NQKV];
__device__ __nv_bfloat16 g_yhi[MTOK * CD],  g_ylo[MTOK * CD];

// ---------------------------------------------------------------------------
// PTX helpers (portable sm_80+ tensor path: cp.async + ldmatrix + mma.sync)
// ---------------------------------------------------------------------------
__device__ __forceinline__ uint32_t smem_u32(const void* p) {
    return (uint32_t)__cvta_generic_to_shared(p);
}
__device__ __forceinline__ void cp16(uint32_t dst_smem, const void* src) {
    asm volatile("cp.async.cg.shared.global [%0], [%1], 16;"
                 :: "r"(dst_smem), "l"(__cvta_generic_to_global(src)) : "memory");
}
__device__ __forceinline__ void ldsm4(uint32_t* r, uint32_t addr) {
    asm volatile("ldmatrix.sync.aligned.m8n8.x4.shared.b16 {%0,%1,%2,%3}, [%4];"
                 : "=r"(r[0]), "=r"(r[1]), "=r"(r[2]), "=r"(r[3]) : "r"(addr));
}
__device__ __forceinline__ void ldsm4t(uint32_t* r, uint32_t addr) {
    asm volatile("ldmatrix.sync.aligned.m8n8.x4.trans.shared.b16 {%0,%1,%2,%3}, [%4];"
                 : "=r"(r[0]), "=r"(r[1]), "=r"(r[2]), "=r"(r[3]) : "r"(addr));
}
__device__ __forceinline__ void mma16816(float* d, const uint32_t* a,
                                         uint32_t b0, uint32_t b1) {
    asm volatile(
        "mma.sync.aligned.m16n8k16.row.col.f32.bf16.bf16.f32 "
        "{%0,%1,%2,%3}, {%4,%5,%6,%7}, {%8,%9}, {%0,%1,%2,%3};"
        : "+f"(d[0]), "+f"(d[1]), "+f"(d[2]), "+f"(d[3])
        : "r"(a[0]), "r"(a[1]), "r"(a[2]), "r"(a[3]), "r"(b0), "r"(b1));
}
// split two floats into packed bf16 hi / bf16 lo registers
__device__ __forceinline__ void split2(float a, float b, uint32_t& hi, uint32_t& lo) {
    __nv_bfloat162 H, L;
    H.x = __float2bfloat16_rn(a);
    H.y = __float2bfloat16_rn(b);
    L.x = __float2bfloat16_rn(a - __bfloat162float(H.x));
    L.y = __float2bfloat16_rn(b - __bfloat162float(H.y));
    hi = *(uint32_t*)&H;
    lo = *(uint32_t*)&L;
}

// ---------------------------------------------------------------------------
// fp32 -> (bf16 hi, bf16 lo) split, 4 elements per thread
// ---------------------------------------------------------------------------
__global__ __launch_bounds__(256)
void split_bf16(const float* __restrict__ in, __nv_bfloat16* __restrict__ hi,
                __nv_bfloat16* __restrict__ lo, int n)
{
    int i = (blockIdx.x * blockDim.x + threadIdx.x) * 4;
    if (i >= n) return;
    float4 v = *(const float4*)(in + i);
    uint32_t h0, l0, h1, l1;
    split2(v.x, v.y, h0, l0);
    split2(v.z, v.w, h1, l1);
    *(uint32_t*)(hi + i)     = h0;
    *(uint32_t*)(hi + i + 2) = h1;
    *(uint32_t*)(lo + i)     = l0;
    *(uint32_t*)(lo + i + 2) = l1;
}

// ---------------------------------------------------------------------------
// mma.sync GEMM with bf16 error-compensated split (3 MMA terms):
//   C[m,n] = sum_k (Ah+Al)[m,k] * (Bh+Bl)[n,k]
// 128x128 CTA tile, 8 warps (32m x 64n each), BK=32, 3-stage cp.async pipe.
// Term-outermost MMA ordering: dependent MMAs on the same acc are 16 apart.
// SPLIT: write output as bf16 hi/lo pair instead of fp32.
// ---------------------------------------------------------------------------
#define TEN_BYTES  8192                 // one tensor tile: 128 * 64B
#define STAGE_BYTES (4 * TEN_BYTES)     // 32 KB
#define NSTAGE 3
#define GEMM_SMEM (NSTAGE * STAGE_BYTES)  // 96 KB

// physical byte offset of (row r, 16B-chunk ch) inside one 64B-row tensor tile
__device__ __forceinline__ uint32_t sw(uint32_t r, uint32_t ch) {
    return r * 64u + (((ch) ^ (r & 3u)) << 4);
}

template <bool BIAS, bool SPLIT>
__global__ __launch_bounds__(256)
void gemm_bf16x3(const __nv_bfloat16* __restrict__ Ah, const __nv_bfloat16* __restrict__ Al,
                 const __nv_bfloat16* __restrict__ Bh, const __nv_bfloat16* __restrict__ Bl,
                 const float* __restrict__ bias, float* __restrict__ C,
                 __nv_bfloat16* __restrict__ Chi, __nv_bfloat16* __restrict__ Clo,
                 int M, int N, int K)
{
    extern __shared__ char smem[];
    const uint32_t sb = smem_u32(smem);
    const int tid = threadIdx.x;
    const int wid = tid >> 5, l = tid & 31;
    const int m0 = blockIdx.y * 128, n0 = blockIdx.x * 128;
    const int NCH = K >> 5;            // BK=32

    const int lt = tid >> 6;           // loader tensor 0..3: Ah, Al, Bh, Bl
    const int lu = tid & 63;
    const __nv_bfloat16* gbase =
        (lt == 0) ? Ah + (size_t)m0 * K :
        (lt == 1) ? Al + (size_t)m0 * K :
        (lt == 2) ? Bh + (size_t)n0 * K :
                    Bl + (size_t)n0 * K;

    auto load_chunk = [&](int c) {
        const uint32_t stage = sb + (uint32_t)(c % NSTAGE) * STAGE_BYTES + lt * TEN_BYTES;
        const int k0 = c << 5;
#pragma unroll
        for (int rr = 0; rr < 2; rr++) {
            const int r = lu * 2 + rr;
            const __nv_bfloat16* gp = gbase + (size_t)r * K + k0;
#pragma unroll
            for (int ch = 0; ch < 4; ch++)
                cp16(stage + sw(r, ch), gp + ch * 8);
        }
        asm volatile("cp.async.commit_group;" ::: "memory");
    };

    const int wm = wid >> 1, wn = wid & 1;

    uint32_t offA[2][2], offB[4][2];
#pragma unroll
    for (int i = 0; i < 2; i++) {
        uint32_t r = wm * 32 + i * 16 + (l & 15);
#pragma unroll
        for (int s = 0; s < 2; s++)
            offA[i][s] = sw(r, s * 2 + (l >> 4));
    }
#pragma unroll
    for (int p = 0; p < 4; p++) {
        uint32_t r = wn * 64 + p * 16 + (l & 7) + ((l >> 4) << 3);
#pragma unroll
        for (int s = 0; s < 2; s++)
            offB[p][s] = sw(r, s * 2 + ((l >> 3) & 1));
    }

    float acc[2][8][4];
#pragma unroll
    for (int i = 0; i < 2; i++)
#pragma unroll
        for (int j = 0; j < 8; j++)
#pragma unroll
            for (int q = 0; q < 4; q++) acc[i][j][q] = 0.0f;

    load_chunk(0);
    load_chunk(1);

    for (int c = 0; c < NCH; c++) {
        if (c + 2 < NCH) {
            load_chunk(c + 2);
            asm volatile("cp.async.wait_group 2;" ::: "memory");
        } else if (c + 1 < NCH) {
            asm volatile("cp.async.wait_group 1;" ::: "memory");
        } else {
            asm volatile("cp.async.wait_group 0;" ::: "memory");
        }
        __syncthreads();

        const uint32_t stage = sb + (uint32_t)(c % NSTAGE) * STAGE_BYTES;
#pragma unroll
        for (int s = 0; s < 2; s++) {
            uint32_t ah[2][4], al2[2][4];
#pragma unroll
            for (int i = 0; i < 2; i++) {
                ldsm4(ah[i],  stage + offA[i][s]);
                ldsm4(al2[i], stage + TEN_BYTES + offA[i][s]);
            }
            uint32_t bh[4][4], bl[4][4];
#pragma unroll
            for (int p = 0; p < 4; p++) {
                ldsm4(bh[p], stage + 2 * TEN_BYTES + offB[p][s]);
                ldsm4(bl[p], stage + 3 * TEN_BYTES + offB[p][s]);
            }
            // term-outermost: dependent MMAs on one acc quad are 16 issues apart
#pragma unroll
            for (int t = 0; t < 3; t++)
#pragma unroll
                for (int i = 0; i < 2; i++)
#pragma unroll
                    for (int j = 0; j < 8; j++) {
                        const int p = j >> 1, hh = (j & 1) * 2;
                        const uint32_t* aa = (t == 2) ? al2[i] : ah[i];
                        const uint32_t* bb = (t == 1) ? &bl[p][hh] : &bh[p][hh];
                        mma16816(acc[i][j], aa, bb[0], bb[1]);
                    }
        }
        __syncthreads();
    }

    const int rowq = l >> 2, colq = (l & 3) * 2;
#pragma unroll
    for (int j = 0; j < 8; j++) {
        const int ccol = n0 + wn * 64 + j * 8 + colq;
        float b0 = 0.f, b1 = 0.f;
        if (BIAS) { b0 = bias[ccol]; b1 = bias[ccol + 1]; }
#pragma unroll
        for (int i = 0; i < 2; i++) {
            const int r = m0 + wm * 32 + i * 16 + rowq;
            if (SPLIT) {
                uint32_t h0, l0, h1, l1;
                split2(acc[i][j][0], acc[i][j][1], h0, l0);
                split2(acc[i][j][2], acc[i][j][3], h1, l1);
                *(uint32_t*)&Chi[(size_t)r * N + ccol]       = h0;
                *(uint32_t*)&Clo[(size_t)r * N + ccol]       = l0;
                *(uint32_t*)&Chi[(size_t)(r + 8) * N + ccol] = h1;
                *(uint32_t*)&Clo[(size_t)(r + 8) * N + ccol] = l1;
            } else {
                float2 v0 = make_float2(acc[i][j][0] + b0, acc[i][j][1] + b1);
                float2 v1 = make_float2(acc[i][j][2] + b0, acc[i][j][3] + b1);
                *(float2*)&C[(size_t)r * N + ccol]       = v0;
                *(float2*)&C[(size_t)(r + 8) * N + ccol] = v1;
            }
        }
    }
}

// ---------------------------------------------------------------------------
// Tensor-core flash attention (bf16 hi/lo x3 terms, fp32 softmax), causal.
// CTA = (qtile 64 rows, head, batch), 4 warps; warp owns 16 q rows.
// smem: Qh|Ql (16KB) + 2 stages of [Kh|Kl|Vh|Vl] (32KB each) = 80KB.
// ---------------------------------------------------------------------------
#define ATT_SMEM (16384 + 2 * 32768)

// 128B-row swizzle: chunk ch (0..7) of row r
__device__ __forceinline__ uint32_t swa(uint32_t r, uint32_t ch) {
    return r * 128u + (((ch) ^ (r & 7u)) << 4);
}

__global__ __launch_bounds__(128)
void attn_kernel(const __nv_bfloat16* __restrict__ qkvhi,
                 const __nv_bfloat16* __restrict__ qkvlo,
                 __nv_bfloat16* __restrict__ yhi, __nv_bfloat16* __restrict__ ylo)
{
    extern __shared__ char smem[];
    const uint32_t sb = smem_u32(smem);
    const int tid = threadIdx.x;
    const int w = tid >> 5, l = tid & 31;
    const int qt = blockIdx.x, h = blockIdx.y, b = blockIdx.z;
    const int q0 = qt * 64;
    const int tok0 = b * SEQ;
    const int koff = h * HD, qoff = CD + h * HD, voff = 2 * CD + h * HD;

    // loader mapping: thread covers row tid>>1, chunks (tid&1)*4 .. +3 (64B)
    const int lr = tid >> 1, lc0 = (tid & 1) * 4;

    auto load_kv = [&](int kt) {
        const int k0 = kt * 64;
        const uint32_t base = sb + 16384 + (uint32_t)(kt & 1) * 32768;
        const size_t rowoff = (size_t)(tok0 + k0 + lr) * NQKV;
        const __nv_bfloat16* s0 = qkvhi + rowoff + koff + lc0 * 8;
        const __nv_bfloat16* s1 = qkvlo + rowoff + koff + lc0 * 8;
        const __nv_bfloat16* s2 = qkvhi + rowoff + voff + lc0 * 8;
        const __nv_bfloat16* s3 = qkvlo + rowoff + voff + lc0 * 8;
#pragma unroll
        for (int c = 0; c < 4; c++) {
            const uint32_t o = swa(lr, lc0 + c);
            cp16(base + o,         s0 + c * 8);
            cp16(base + 8192 + o,  s1 + c * 8);
            cp16(base + 16384 + o, s2 + c * 8);
            cp16(base + 24576 + o, s3 + c * 8);
        }
        asm volatile("cp.async.commit_group;" ::: "memory");
    };

    // prologue: Q tile + kv tile 0 in group0; kv tile 1 in group1
    {
        const size_t rowoff = (size_t)(tok0 + q0 + lr) * NQKV;
        const __nv_bfloat16* s0 = qkvhi + rowoff + qoff + lc0 * 8;
        const __nv_bfloat16* s1 = qkvlo + rowoff + qoff + lc0 * 8;
#pragma unroll
        for (int c = 0; c < 4; c++) {
            const uint32_t o = swa(lr, lc0 + c);
            cp16(sb + o,        s0 + c * 8);
            cp16(sb + 8192 + o, s1 + c * 8);
        }
    }
    load_kv(0);
    if (qt >= 1) load_kv(1);

    // lane address components
    const uint32_t qrow = w * 16 + (l & 15);
    const uint32_t qch  = l >> 4;
    const uint32_t krow = (l & 7) + ((l >> 4) << 3);
    const uint32_t kch  = (l >> 3) & 1;
    const uint32_t vrow = (l & 7) + (((l >> 3) & 1) << 3);
    const uint32_t vch  = l >> 4;

    uint32_t qh[4][4], ql[4][4];
    float o[8][4];
#pragma unroll
    for (int j = 0; j < 8; j++)
#pragma unroll
        for (int q = 0; q < 4; q++) o[j][q] = 0.0f;
    float sm0 = -1e30f, sm1 = -1e30f, sl0 = 0.0f, sl1 = 0.0f;

    const int r0 = w * 16 + (l >> 2);   // within q tile
    const int r1 = r0 + 8;
    const float scale = 0.125f;

    for (int kt = 0; kt <= qt; kt++) {
        if (kt < qt) asm volatile("cp.async.wait_group 1;" ::: "memory");
        else         asm volatile("cp.async.wait_group 0;" ::: "memory");
        __syncthreads();

        if (kt == 0) {
#pragma unroll
            for (int s = 0; s < 4; s++) {
                ldsm4(qh[s], sb + swa(qrow, s * 2 + qch));
                ldsm4(ql[s], sb + 8192 + swa(qrow, s * 2 + qch));
            }
        }

        const uint32_t stage = sb + 16384 + (uint32_t)(kt & 1) * 32768;

        // ---- S = Q K^T (3 terms) ----
        float sacc[8][4];
#pragma unroll
        for (int j = 0; j < 8; j++)
#pragma unroll
            for (int q = 0; q < 4; q++) sacc[j][q] = 0.0f;

#pragma unroll
        for (int s = 0; s < 4; s++) {
#pragma unroll
            for (int p = 0; p < 4; p++) {
                uint32_t kh[4], kl[4];
                const uint32_t ko = swa(p * 16 + krow, s * 2 + kch);
                ldsm4(kh, stage + ko);
                ldsm4(kl, stage + 8192 + ko);
#pragma unroll
                for (int jj = 0; jj < 2; jj++) {
                    const int j = p * 2 + jj;
                    mma16816(sacc[j], qh[s], kh[jj * 2], kh[jj * 2 + 1]);
                    mma16816(sacc[j], qh[s], kl[jj * 2], kl[jj * 2 + 1]);
                    mma16816(sacc[j], ql[s], kh[jj * 2], kh[jj * 2 + 1]);
                }
            }
        }

        // ---- online softmax (registers only) ----
        const bool diag = (kt == qt);
        float ml0 = -1e30f, ml1 = -1e30f;
#pragma unroll
        for (int j = 0; j < 8; j++) {
            const int c0 = j * 8 + (l & 3) * 2;
            float v0 = sacc[j][0] * scale, v1 = sacc[j][1] * scale;
            float v2 = sacc[j][2] * scale, v3 = sacc[j][3] * scale;
            if (diag) {
                if (c0     > r0) v0 = -1e30f;
                if (c0 + 1 > r0) v1 = -1e30f;
                if (c0     > r1) v2 = -1e30f;
                if (c0 + 1 > r1) v3 = -1e30f;
            }
            sacc[j][0] = v0; sacc[j][1] = v1; sacc[j][2] = v2; sacc[j][3] = v3;
            ml0 = fmaxf(ml0, fmaxf(v0, v1));
            ml1 = fmaxf(ml1, fmaxf(v2, v3));
        }
        ml0 = fmaxf(ml0, __shfl_xor_sync(0xffffffffu, ml0, 1));
        ml0 = fmaxf(ml0, __shfl_xor_sync(0xffffffffu, ml0, 2));
        ml1 = fmaxf(ml1, __shfl_xor_sync(0xffffffffu, ml1, 1));
        ml1 = fmaxf(ml1, __shfl_xor_sync(0xffffffffu, ml1, 2));
        const float mn0 = fmaxf(sm0, ml0), mn1 = fmaxf(sm1, ml1);
        const float cf0 = __expf(sm0 - mn0), cf1 = __expf(sm1 - mn1);
        sm0 = mn0; sm1 = mn1;

        float rs0 = 0.0f, rs1 = 0.0f;
#pragma unroll
        for (int j = 0; j < 8; j++) {
            sacc[j][0] = __expf(sacc[j][0] - mn0);
            sacc[j][1] = __expf(sacc[j][1] - mn0);
            sacc[j][2] = __expf(sacc[j][2] - mn1);
            sacc[j][3] = __expf(sacc[j][3] - mn1);
            rs0 += sacc[j][0] + sacc[j][1];
            rs1 += sacc[j][2] + sacc[j][3];
        }
        rs0 += __shfl_xor_sync(0xffffffffu, rs0, 1);
        rs0 += __shfl_xor_sync(0xffffffffu, rs0, 2);
        rs1 += __shfl_xor_sync(0xffffffffu, rs1, 1);
        rs1 += __shfl_xor_sync(0xffffffffu, rs1, 2);
        sl0 = sl0 * cf0 + rs0;
        sl1 = sl1 * cf1 + rs1;

#pragma unroll
        for (int j = 0; j < 8; j++) {
            o[j][0] *= cf0; o[j][1] *= cf0;
            o[j][2] *= cf1; o[j][3] *= cf1;
        }

        // ---- P fragments (acc layout == A-fragment layout) ----
        uint32_t ph[4][4], pl[4][4];
#pragma unroll
        for (int t = 0; t < 4; t++) {
            split2(sacc[2 * t][0],     sacc[2 * t][1],     ph[t][0], pl[t][0]);
            split2(sacc[2 * t][2],     sacc[2 * t][3],     ph[t][1], pl[t][1]);
            split2(sacc[2 * t + 1][0], sacc[2 * t + 1][1], ph[t][2], pl[t][2]);
            split2(sacc[2 * t + 1][2], sacc[2 * t + 1][3], ph[t][3], pl[t][3]);
        }

        // ---- O += P V (3 terms), V^T via ldmatrix.trans ----
#pragma unroll
        for (int t = 0; t < 4; t++) {
#pragma unroll
            for (int p = 0; p < 4; p++) {
                uint32_t vh[4], vl[4];
                const uint32_t vo = swa(t * 16 + vrow, p * 2 + vch);
                ldsm4t(vh, stage + 16384 + vo);
                ldsm4t(vl, stage + 24576 + vo);
#pragma unroll
                for (int jj = 0; jj < 2; jj++) {
                    const int j = p * 2 + jj;
                    mma16816(o[j], ph[t], vh[jj * 2], vh[jj * 2 + 1]);
                    mma16816(o[j], ph[t], vl[jj * 2], vl[jj * 2 + 1]);
                    mma16816(o[j], pl[t], vh[jj * 2], vh[jj * 2 + 1]);
                }
            }
        }

        __syncthreads();
        if (kt + 2 <= qt) load_kv(kt + 2);
    }

    // ---- finalize: divide by l, split to bf16 hi/lo, store ----
    const float inv0 = 1.0f / sl0, inv1 = 1.0f / sl1;
    const size_t row0 = (size_t)(tok0 + q0 + r0) * CD + h * HD;
    const size_t row1 = (size_t)(tok0 + q0 + r1) * CD + h * HD;
#pragma unroll
    for (int j = 0; j < 8; j++) {
        const int c0 = j * 8 + (l & 3) * 2;
        uint32_t h0, l0w, h1, l1w;
        split2(o[j][0] * inv0, o[j][1] * inv0, h0, l0w);
        split2(o[j][2] * inv1, o[j][3] * inv1, h1, l1w);
        *(uint32_t*)&yhi[row0 + c0] = h0;
        *(uint32_t*)&ylo[row0 + c0] = l0w;
        *(uint32_t*)&yhi[row1 + c0] = h1;
        *(uint32_t*)&ylo[row1 + c0] = l1w;
    }
}

// ---------------------------------------------------------------------------
extern "C" void kernel_launch(void* const* d_in, const int* in_sizes, int n_in,
                              void* d_out, int out_size)
{
    const float* x      = (const float*)d_in[0];
    const float* w_attn = (const float*)d_in[1];
    const float* w_proj = (const float*)d_in[2];
    const float* b_proj = (const float*)d_in[3];
    float* out = (float*)d_out;

    __nv_bfloat16 *xhi, *xlo, *wahi, *walo, *wphi, *wplo, *qkvhi, *qkvlo, *yhi, *ylo;
    cudaGetSymbolAddress((void**)&xhi,   g_xhi);
    cudaGetSymbolAddress((void**)&xlo,   g_xlo);
    cudaGetSymbolAddress((void**)&wahi,  g_wahi);
    cudaGetSymbolAddress((void**)&walo,  g_walo);
    cudaGetSymbolAddress((void**)&wphi,  g_wphi);
    cudaGetSymbolAddress((void**)&wplo,  g_wplo);
    cudaGetSymbolAddress((void**)&qkvhi, g_qkvhi);
    cudaGetSymbolAddress((void**)&qkvlo, g_qkvlo);
    cudaGetSymbolAddress((void**)&yhi,   g_yhi);
    cudaGetSymbolAddress((void**)&ylo,   g_ylo);

    cudaFuncSetAttribute(attn_kernel,
                         cudaFuncAttributeMaxDynamicSharedMemorySize, ATT_SMEM);
    cudaFuncSetAttribute(gemm_bf16x3<false, true>,
                         cudaFuncAttributeMaxDynamicSharedMemorySize, GEMM_SMEM);
    cudaFuncSetAttribute(gemm_bf16x3<true, false>,
                         cudaFuncAttributeMaxDynamicSharedMemorySize, GEMM_SMEM);

    // 0) split inputs into bf16 hi/lo
    split_bf16<<<(MTOK * CD / 4 + 255) / 256, 256>>>(x, xhi, xlo, MTOK * CD);
    split_bf16<<<(NQKV * CD / 4 + 255) / 256, 256>>>(w_attn, wahi, walo, NQKV * CD);
    split_bf16<<<(CD * CD / 4 + 255) / 256, 256>>>(w_proj, wphi, wplo, CD * CD);

    // 1) QKV projection -> qkv hi/lo (epilogue split)
    gemm_bf16x3<false, true><<<dim3(NQKV / 128, MTOK / 128), 256, GEMM_SMEM>>>(
        xhi, xlo, wahi, walo, nullptr, nullptr, qkvhi, qkvlo, MTOK, NQKV, CD);

    // 2) tensor-core causal flash attention -> y hi/lo
    attn_kernel<<<dim3(SEQ / 64, NH, BATCH), 128, ATT_SMEM>>>(qkvhi, qkvlo, yhi, ylo);

    // 3) output projection: out = y @ w_proj^T + b_proj (fp32 out)
    gemm_bf16x3<true, false><<<dim3(CD / 128, MTOK / 128), 256, GEMM_SMEM>>>(
        yhi, ylo, wphi, wplo, b_proj, out, nullptr, nullptr, MTOK, CD, CD);
}

// round 6
// speedup vs baseline: 4.8628x; 2.2904x over previous
#include <cuda_runtime.h>
#include <cuda_fp16.h>
#include <cstdint>

// Problem constants
#define BATCH 8
#define SEQ   1024
#define CD    1024
#define NH    16
#define HD    64
#define MTOK  (BATCH * SEQ)      // 8192 tokens
#define NQKV  (3 * CD)           // 3072

// Scratch (no allocations allowed -> __device__ globals)
__device__ __half g_xh[MTOK * CD];
__device__ __half g_wah[NQKV * CD];
__device__ __half g_wph[CD * CD];
__device__ __half g_qkvh[MTOK * NQKV];
__device__ __half g_yh[MTOK * CD];

// ---------------------------------------------------------------------------
// PTX helpers (portable sm_80+ tensor path: cp.async + ldmatrix + mma.sync)
// ---------------------------------------------------------------------------
__device__ __forceinline__ uint32_t smem_u32(const void* p) {
    return (uint32_t)__cvta_generic_to_shared(p);
}
__device__ __forceinline__ void cp16(uint32_t dst_smem, const void* src) {
    asm volatile("cp.async.cg.shared.global [%0], [%1], 16;"
                 :: "r"(dst_smem), "l"(__cvta_generic_to_global(src)) : "memory");
}
__device__ __forceinline__ void ldsm4(uint32_t* r, uint32_t addr) {
    asm volatile("ldmatrix.sync.aligned.m8n8.x4.shared.b16 {%0,%1,%2,%3}, [%4];"
                 : "=r"(r[0]), "=r"(r[1]), "=r"(r[2]), "=r"(r[3]) : "r"(addr));
}
__device__ __forceinline__ void ldsm4t(uint32_t* r, uint32_t addr) {
    asm volatile("ldmatrix.sync.aligned.m8n8.x4.trans.shared.b16 {%0,%1,%2,%3}, [%4];"
                 : "=r"(r[0]), "=r"(r[1]), "=r"(r[2]), "=r"(r[3]) : "r"(addr));
}
__device__ __forceinline__ void mma16816(float* d, const uint32_t* a,
                                         uint32_t b0, uint32_t b1) {
    asm volatile(
        "mma.sync.aligned.m16n8k16.row.col.f32.f16.f16.f32 "
        "{%0,%1,%2,%3}, {%4,%5,%6,%7}, {%8,%9}, {%0,%1,%2,%3};"
        : "+f"(d[0]), "+f"(d[1]), "+f"(d[2]), "+f"(d[3])
        : "r"(a[0]), "r"(a[1]), "r"(a[2]), "r"(a[3]), "r"(b0), "r"(b1));
}
__device__ __forceinline__ uint32_t pack2(float a, float b) {
    __half2 h = __floats2half2_rn(a, b);
    return *(uint32_t*)&h;
}

// 128B-row swizzle: 16B chunk ch (0..7) of row r
__device__ __forceinline__ uint32_t swa(uint32_t r, uint32_t ch) {
    return r * 128u + (((ch) ^ (r & 7u)) << 4);
}

// ---------------------------------------------------------------------------
// fp32 -> fp16 convert, 4 elements per thread
// ---------------------------------------------------------------------------
__global__ __launch_bounds__(256)
void cvt_f16(const float* __restrict__ in, __half* __restrict__ out, int n)
{
    int i = (blockIdx.x * blockDim.x + threadIdx.x) * 4;
    if (i >= n) return;
    float4 v = *(const float4*)(in + i);
    *(uint32_t*)(out + i)     = pack2(v.x, v.y);
    *(uint32_t*)(out + i + 2) = pack2(v.z, v.w);
}

// ---------------------------------------------------------------------------
// fp16 mma.sync GEMM: C[m,n] = sum_k A[m,k] * B[n,k]  (+bias)
// 128x128 CTA tile, 8 warps (32m x 64n each), BK=64, 3-stage cp.async pipe.
// OUTH: write fp16 output instead of fp32.
// ---------------------------------------------------------------------------
#define TEN_BYTES  16384                // 128 rows x 128B (64 fp16 cols)
#define STAGE_BYTES (2 * TEN_BYTES)     // A + B = 32 KB
#define NSTAGE 3
#define GEMM_SMEM (NSTAGE * STAGE_BYTES)  // 96 KB

template <bool BIAS, bool OUTH>
__global__ __launch_bounds__(256, 2)
void gemm_f16(const __half* __restrict__ A, const __half* __restrict__ B,
              const float* __restrict__ bias, float* __restrict__ C,
              __half* __restrict__ Ch, int M, int N, int K)
{
    extern __shared__ char smem[];
    const uint32_t sb = smem_u32(smem);
    const int tid = threadIdx.x;
    const int wid = tid >> 5, l = tid & 31;
    const int m0 = blockIdx.y * 128, n0 = blockIdx.x * 128;
    const int NCH = K >> 6;            // BK=64

    // loader: 128 threads on A, 128 on B; each thread owns one 128B row
    const int lt = tid >> 7;           // 0 = A, 1 = B
    const int lr = tid & 127;
    const __half* gbase = (lt == 0) ? A + (size_t)(m0 + lr) * K
                                    : B + (size_t)(n0 + lr) * K;

    auto load_chunk = [&](int c) {
        const uint32_t stage = sb + (uint32_t)(c % NSTAGE) * STAGE_BYTES + lt * TEN_BYTES;
        const __half* gp = gbase + (c << 6);
#pragma unroll
        for (int ch = 0; ch < 8; ch++)
            cp16(stage + swa(lr, ch), gp + ch * 8);
        asm volatile("cp.async.commit_group;" ::: "memory");
    };

    const int wm = wid >> 1, wn = wid & 1;

    // fragment offsets within a tensor tile (chunk index added per s-step)
    const uint32_t arow = wm * 32 + (l & 15);
    const uint32_t ach  = l >> 4;
    const uint32_t brow = wn * 64 + (l & 7) + ((l >> 4) << 3);
    const uint32_t bch  = (l >> 3) & 1;

    float acc[2][8][4];
#pragma unroll
    for (int i = 0; i < 2; i++)
#pragma unroll
        for (int j = 0; j < 8; j++)
#pragma unroll
            for (int q = 0; q < 4; q++) acc[i][j][q] = 0.0f;

    load_chunk(0);
    load_chunk(1);

    for (int c = 0; c < NCH; c++) {
        if (c + 2 < NCH) {
            load_chunk(c + 2);
            asm volatile("cp.async.wait_group 2;" ::: "memory");
        } else if (c + 1 < NCH) {
            asm volatile("cp.async.wait_group 1;" ::: "memory");
        } else {
            asm volatile("cp.async.wait_group 0;" ::: "memory");
        }
        __syncthreads();

        const uint32_t stage = sb + (uint32_t)(c % NSTAGE) * STAGE_BYTES;
#pragma unroll
        for (int s = 0; s < 4; s++) {
            uint32_t ah[2][4];
#pragma unroll
            for (int i = 0; i < 2; i++)
                ldsm4(ah[i], stage + swa(arow + i * 16, s * 2 + ach));
            uint32_t bh[4][4];
#pragma unroll
            for (int p = 0; p < 4; p++)
                ldsm4(bh[p], stage + TEN_BYTES + swa(brow + p * 16, s * 2 + bch));
#pragma unroll
            for (int i = 0; i < 2; i++)
#pragma unroll
                for (int j = 0; j < 8; j++) {
                    const int p = j >> 1, hh = (j & 1) * 2;
                    mma16816(acc[i][j], ah[i], bh[p][hh], bh[p][hh + 1]);
                }
        }
        __syncthreads();
    }

    const int rowq = l >> 2, colq = (l & 3) * 2;
#pragma unroll
    for (int j = 0; j < 8; j++) {
        const int ccol = n0 + wn * 64 + j * 8 + colq;
        float b0 = 0.f, b1 = 0.f;
        if (BIAS) { b0 = bias[ccol]; b1 = bias[ccol + 1]; }
#pragma unroll
        for (int i = 0; i < 2; i++) {
            const int r = m0 + wm * 32 + i * 16 + rowq;
            if (OUTH) {
                *(uint32_t*)&Ch[(size_t)r * N + ccol] =
                    pack2(acc[i][j][0], acc[i][j][1]);
                *(uint32_t*)&Ch[(size_t)(r + 8) * N + ccol] =
                    pack2(acc[i][j][2], acc[i][j][3]);
            } else {
                float2 v0 = make_float2(acc[i][j][0] + b0, acc[i][j][1] + b1);
                float2 v1 = make_float2(acc[i][j][2] + b0, acc[i][j][3] + b1);
                *(float2*)&C[(size_t)r * N + ccol]       = v0;
                *(float2*)&C[(size_t)(r + 8) * N + ccol] = v1;
            }
        }
    }
}

// ---------------------------------------------------------------------------
// Tensor-core flash attention (fp16, fp32 softmax), causal.
// CTA = (qtile 64 rows, head, batch), 4 warps; warp owns 16 q rows.
// smem: Q (8KB) + 2 stages of [K|V] (16KB each) = 40KB.
// ---------------------------------------------------------------------------
#define ATT_SMEM (8192 + 2 * 16384)

__global__ __launch_bounds__(128)
void attn_kernel(const __half* __restrict__ qkvh,
                 __half* __restrict__ yh)
{
    extern __shared__ char smem[];
    const uint32_t sb = smem_u32(smem);
    const int tid = threadIdx.x;
    const int w = tid >> 5, l = tid & 31;
    const int qt = blockIdx.x, h = blockIdx.y, b = blockIdx.z;
    const int q0 = qt * 64;
    const int tok0 = b * SEQ;
    const int koff = h * HD, qoff = CD + h * HD, voff = 2 * CD + h * HD;

    // loader: thread covers row tid>>1, chunks (tid&1)*4 .. +3 (64B)
    const int lr = tid >> 1, lc0 = (tid & 1) * 4;

    auto load_kv = [&](int kt) {
        const int k0 = kt * 64;
        const uint32_t base = sb + 8192 + (uint32_t)(kt & 1) * 16384;
        const size_t rowoff = (size_t)(tok0 + k0 + lr) * NQKV;
        const __half* s0 = qkvh + rowoff + koff + lc0 * 8;
        const __half* s1 = qkvh + rowoff + voff + lc0 * 8;
#pragma unroll
        for (int c = 0; c < 4; c++) {
            const uint32_t o = swa(lr, lc0 + c);
            cp16(base + o,        s0 + c * 8);
            cp16(base + 8192 + o, s1 + c * 8);
        }
        asm volatile("cp.async.commit_group;" ::: "memory");
    };

    // prologue: Q tile + kv tile 0 in group0; kv tile 1 in group1
    {
        const size_t rowoff = (size_t)(tok0 + q0 + lr) * NQKV;
        const __half* s0 = qkvh + rowoff + qoff + lc0 * 8;
#pragma unroll
        for (int c = 0; c < 4; c++)
            cp16(sb + swa(lr, lc0 + c), s0 + c * 8);
    }
    load_kv(0);
    if (qt >= 1) load_kv(1);

    const uint32_t qrow = w * 16 + (l & 15);
    const uint32_t qch  = l >> 4;
    const uint32_t krow = (l & 7) + ((l >> 4) << 3);
    const uint32_t kch  = (l >> 3) & 1;
    const uint32_t vrow = (l & 7) + (((l >> 3) & 1) << 3);
    const uint32_t vch  = l >> 4;

    uint32_t qh[4][4];
    float o[8][4];
#pragma unroll
    for (int j = 0; j < 8; j++)
#pragma unroll
        for (int q = 0; q < 4; q++) o[j][q] = 0.0f;
    float sm0 = -1e30f, sm1 = -1e30f, sl0 = 0.0f, sl1 = 0.0f;

    const int r0 = w * 16 + (l >> 2);   // within q tile
    const int r1 = r0 + 8;
    const float scale = 0.125f;

    for (int kt = 0; kt <= qt; kt++) {
        if (kt < qt) asm volatile("cp.async.wait_group 1;" ::: "memory");
        else         asm volatile("cp.async.wait_group 0;" ::: "memory");
        __syncthreads();

        if (kt == 0) {
#pragma unroll
            for (int s = 0; s < 4; s++)
                ldsm4(qh[s], sb + swa(qrow, s * 2 + qch));
        }

        const uint32_t stage = sb + 8192 + (uint32_t)(kt & 1) * 16384;

        // ---- S = Q K^T ----
        float sacc[8][4];
#pragma unroll
        for (int j = 0; j < 8; j++)
#pragma unroll
            for (int q = 0; q < 4; q++) sacc[j][q] = 0.0f;

#pragma unroll
        for (int s = 0; s < 4; s++) {
#pragma unroll
            for (int p = 0; p < 4; p++) {
                uint32_t kh[4];
                ldsm4(kh, stage + swa(p * 16 + krow, s * 2 + kch));
#pragma unroll
                for (int jj = 0; jj < 2; jj++)
                    mma16816(sacc[p * 2 + jj], qh[s], kh[jj * 2], kh[jj * 2 + 1]);
            }
        }

        // ---- online softmax (registers only) ----
        const bool diag = (kt == qt);
        float ml0 = -1e30f, ml1 = -1e30f;
#pragma unroll
        for (int j = 0; j < 8; j++) {
            const int c0 = j * 8 + (l & 3) * 2;
            float v0 = sacc[j][0] * scale, v1 = sacc[j][1] * scale;
            float v2 = sacc[j][2] * scale, v3 = sacc[j][3] * scale;
            if (diag) {
                if (c0     > r0) v0 = -1e30f;
                if (c0 + 1 > r0) v1 = -1e30f;
                if (c0     > r1) v2 = -1e30f;
                if (c0 + 1 > r1) v3 = -1e30f;
            }
            sacc[j][0] = v0; sacc[j][1] = v1; sacc[j][2] = v2; sacc[j][3] = v3;
            ml0 = fmaxf(ml0, fmaxf(v0, v1));
            ml1 = fmaxf(ml1, fmaxf(v2, v3));
        }
        ml0 = fmaxf(ml0, __shfl_xor_sync(0xffffffffu, ml0, 1));
        ml0 = fmaxf(ml0, __shfl_xor_sync(0xffffffffu, ml0, 2));
        ml1 = fmaxf(ml1, __shfl_xor_sync(0xffffffffu, ml1, 1));
        ml1 = fmaxf(ml1, __shfl_xor_sync(0xffffffffu, ml1, 2));
        const float mn0 = fmaxf(sm0, ml0), mn1 = fmaxf(sm1, ml1);
        const float cf0 = __expf(sm0 - mn0), cf1 = __expf(sm1 - mn1);
        sm0 = mn0; sm1 = mn1;

        float rs0 = 0.0f, rs1 = 0.0f;
#pragma unroll
        for (int j = 0; j < 8; j++) {
            sacc[j][0] = __expf(sacc[j][0] - mn0);
            sacc[j][1] = __expf(sacc[j][1] - mn0);
            sacc[j][2] = __expf(sacc[j][2] - mn1);
            sacc[j][3] = __expf(sacc[j][3] - mn1);
            rs0 += sacc[j][0] + sacc[j][1];
            rs1 += sacc[j][2] + sacc[j][3];
        }
        rs0 += __shfl_xor_sync(0xffffffffu, rs0, 1);
        rs0 += __shfl_xor_sync(0xffffffffu, rs0, 2);
        rs1 += __shfl_xor_sync(0xffffffffu, rs1, 1);
        rs1 += __shfl_xor_sync(0xffffffffu, rs1, 2);
        sl0 = sl0 * cf0 + rs0;
        sl1 = sl1 * cf1 + rs1;

#pragma unroll
        for (int j = 0; j < 8; j++) {
            o[j][0] *= cf0; o[j][1] *= cf0;
            o[j][2] *= cf1; o[j][3] *= cf1;
        }

        // ---- P fragments (acc layout == A-fragment layout) ----
        uint32_t ph[4][4];
#pragma unroll
        for (int t = 0; t < 4; t++) {
            ph[t][0] = pack2(sacc[2 * t][0],     sacc[2 * t][1]);
            ph[t][1] = pack2(sacc[2 * t][2],     sacc[2 * t][3]);
            ph[t][2] = pack2(sacc[2 * t + 1][0], sacc[2 * t + 1][1]);
            ph[t][3] = pack2(sacc[2 * t + 1][2], sacc[2 * t + 1][3]);
        }

        // ---- O += P V, V^T via ldmatrix.trans ----
#pragma unroll
        for (int t = 0; t < 4; t++) {
#pragma unroll
            for (int p = 0; p < 4; p++) {
                uint32_t vh[4];
                ldsm4t(vh, stage + 8192 + swa(t * 16 + vrow, p * 2 + vch));
#pragma unroll
                for (int jj = 0; jj < 2; jj++)
                    mma16816(o[p * 2 + jj], ph[t], vh[jj * 2], vh[jj * 2 + 1]);
            }
        }

        __syncthreads();
        if (kt + 2 <= qt) load_kv(kt + 2);
    }

    // ---- finalize: divide by l, store fp16 ----
    const float inv0 = 1.0f / sl0, inv1 = 1.0f / sl1;
    const size_t row0 = (size_t)(tok0 + q0 + r0) * CD + h * HD;
    const size_t row1 = (size_t)(tok0 + q0 + r1) * CD + h * HD;
#pragma unroll
    for (int j = 0; j < 8; j++) {
        const int c0 = j * 8 + (l & 3) * 2;
        *(uint32_t*)&yh[row0 + c0] = pack2(o[j][0] * inv0, o[j][1] * inv0);
        *(uint32_t*)&yh[row1 + c0] = pack2(o[j][2] * inv1, o[j][3] * inv1);
    }
}

// ---------------------------------------------------------------------------
extern "C" void kernel_launch(void* const* d_in, const int* in_sizes, int n_in,
                              void* d_out, int out_size)
{
    const float* x      = (const float*)d_in[0];
    const float* w_attn = (const float*)d_in[1];
    const float* w_proj = (const float*)d_in[2];
    const float* b_proj = (const float*)d_in[3];
    float* out = (float*)d_out;

    __half *xh, *wah, *wph, *qkvh, *yh;
    cudaGetSymbolAddress((void**)&xh,   g_xh);
    cudaGetSymbolAddress((void**)&wah,  g_wah);
    cudaGetSymbolAddress((void**)&wph,  g_wph);
    cudaGetSymbolAddress((void**)&qkvh, g_qkvh);
    cudaGetSymbolAddress((void**)&yh,   g_yh);

    cudaFuncSetAttribute(attn_kernel,
                         cudaFuncAttributeMaxDynamicSharedMemorySize, ATT_SMEM);
    cudaFuncSetAttribute(gemm_f16<false, true>,
                         cudaFuncAttributeMaxDynamicSharedMemorySize, GEMM_SMEM);
    cudaFuncSetAttribute(gemm_f16<true, false>,
                         cudaFuncAttributeMaxDynamicSharedMemorySize, GEMM_SMEM);

    // 0) convert inputs to fp16
    cvt_f16<<<(MTOK * CD / 4 + 255) / 256, 256>>>(x, xh, MTOK * CD);
    cvt_f16<<<(NQKV * CD / 4 + 255) / 256, 256>>>(w_attn, wah, NQKV * CD);
    cvt_f16<<<(CD * CD / 4 + 255) / 256, 256>>>(w_proj, wph, CD * CD);

    // 1) QKV projection -> qkv fp16
    gemm_f16<false, true><<<dim3(NQKV / 128, MTOK / 128), 256, GEMM_SMEM>>>(
        xh, wah, nullptr, nullptr, qkvh, MTOK, NQKV, CD);

    // 2) tensor-core causal flash attention -> y fp16
    attn_kernel<<<dim3(SEQ / 64, NH, BATCH), 128, ATT_SMEM>>>(qkvh, yh);

    // 3) output projection: out = y @ w_proj^T + b_proj (fp32 out)
    gemm_f16<true, false><<<dim3(CD / 128, MTOK / 128), 256, GEMM_SMEM>>>(
        yh, wph, b_proj, out, nullptr, MTOK, CD, CD);
}

// round 7
// speedup vs baseline: 4.9594x; 1.0199x over previous
#include <cuda_runtime.h>
#include <cuda_fp16.h>
#include <cstdint>

// Problem constants
#define BATCH 8
#define SEQ   1024
#define CD    1024
#define NH    16
#define HD    64
#define MTOK  (BATCH * SEQ)      // 8192 tokens
#define NQKV  (3 * CD)           // 3072

// Scratch (no allocations allowed -> __device__ globals)
__device__ __half g_xh[MTOK * CD];
__device__ __half g_wah[NQKV * CD];
__device__ __half g_wph[CD * CD];
__device__ __half g_qkvh[MTOK * NQKV];
__device__ __half g_yh[MTOK * CD];

// ---------------------------------------------------------------------------
// PTX helpers (portable sm_80+ tensor path: cp.async + ldmatrix + mma.sync)
// ---------------------------------------------------------------------------
__device__ __forceinline__ uint32_t smem_u32(const void* p) {
    return (uint32_t)__cvta_generic_to_shared(p);
}
__device__ __forceinline__ void cp16(uint32_t dst_smem, const void* src) {
    asm volatile("cp.async.cg.shared.global [%0], [%1], 16;"
                 :: "r"(dst_smem), "l"(__cvta_generic_to_global(src)) : "memory");
}
__device__ __forceinline__ void ldsm4(uint32_t* r, uint32_t addr) {
    asm volatile("ldmatrix.sync.aligned.m8n8.x4.shared.b16 {%0,%1,%2,%3}, [%4];"
                 : "=r"(r[0]), "=r"(r[1]), "=r"(r[2]), "=r"(r[3]) : "r"(addr));
}
__device__ __forceinline__ void ldsm4t(uint32_t* r, uint32_t addr) {
    asm volatile("ldmatrix.sync.aligned.m8n8.x4.trans.shared.b16 {%0,%1,%2,%3}, [%4];"
                 : "=r"(r[0]), "=r"(r[1]), "=r"(r[2]), "=r"(r[3]) : "r"(addr));
}
__device__ __forceinline__ void mma16816(float* d, const uint32_t* a,
                                         uint32_t b0, uint32_t b1) {
    asm volatile(
        "mma.sync.aligned.m16n8k16.row.col.f32.f16.f16.f32 "
        "{%0,%1,%2,%3}, {%4,%5,%6,%7}, {%8,%9}, {%0,%1,%2,%3};"
        : "+f"(d[0]), "+f"(d[1]), "+f"(d[2]), "+f"(d[3])
        : "r"(a[0]), "r"(a[1]), "r"(a[2]), "r"(a[3]), "r"(b0), "r"(b1));
}
__device__ __forceinline__ uint32_t pack2(float a, float b) {
    __half2 h = __floats2half2_rn(a, b);
    return *(uint32_t*)&h;
}

// 128B-row swizzle: 16B chunk ch (0..7) of row r
__device__ __forceinline__ uint32_t swa(uint32_t r, uint32_t ch) {
    return r * 128u + (((ch) ^ (r & 7u)) << 4);
}

// ---------------------------------------------------------------------------
// fp32 -> fp16 convert, 4 elements per thread
// ---------------------------------------------------------------------------
__global__ __launch_bounds__(256)
void cvt_f16(const float* __restrict__ in, __half* __restrict__ out, int n)
{
    int i = (blockIdx.x * blockDim.x + threadIdx.x) * 4;
    if (i >= n) return;
    float4 v = *(const float4*)(in + i);
    *(uint32_t*)(out + i)     = pack2(v.x, v.y);
    *(uint32_t*)(out + i + 2) = pack2(v.z, v.w);
}

// ---------------------------------------------------------------------------
// fp16 mma.sync GEMM: C[m,n] = sum_k A[m,k] * B[n,k]  (+bias)
// 128x128 CTA tile, 8 warps (32m x 64n each), BK=64, 3-stage cp.async pipe.
// Fragment double-buffering: s+1's ldmatrix issued before s's MMAs.
// ---------------------------------------------------------------------------
#define TEN_BYTES  16384                // 128 rows x 128B (64 fp16 cols)
#define STAGE_BYTES (2 * TEN_BYTES)     // A + B = 32 KB
#define NSTAGE 3
#define GEMM_SMEM (NSTAGE * STAGE_BYTES)  // 96 KB

template <bool BIAS, bool OUTH>
__global__ __launch_bounds__(256, 2)
void gemm_f16(const __half* __restrict__ A, const __half* __restrict__ B,
              const float* __restrict__ bias, float* __restrict__ C,
              __half* __restrict__ Ch, int M, int N, int K)
{
    extern __shared__ char smem[];
    const uint32_t sb = smem_u32(smem);
    const int tid = threadIdx.x;
    const int wid = tid >> 5, l = tid & 31;
    const int m0 = blockIdx.y * 128, n0 = blockIdx.x * 128;
    const int NCH = K >> 6;            // BK=64

    // loader: 128 threads on A, 128 on B; each thread owns one 128B row
    const int lt = tid >> 7;           // 0 = A, 1 = B
    const int lr = tid & 127;
    const __half* gbase = (lt == 0) ? A + (size_t)(m0 + lr) * K
                                    : B + (size_t)(n0 + lr) * K;

    auto load_chunk = [&](int c) {
        const uint32_t stage = sb + (uint32_t)(c % NSTAGE) * STAGE_BYTES + lt * TEN_BYTES;
        const __half* gp = gbase + (c << 6);
#pragma unroll
        for (int ch = 0; ch < 8; ch++)
            cp16(stage + swa(lr, ch), gp + ch * 8);
        asm volatile("cp.async.commit_group;" ::: "memory");
    };

    const int wm = wid >> 1, wn = wid & 1;

    const uint32_t arow = wm * 32 + (l & 15);
    const uint32_t ach  = l >> 4;
    const uint32_t brow = wn * 64 + (l & 7) + ((l >> 4) << 3);
    const uint32_t bch  = (l >> 3) & 1;

    float acc[2][8][4];
#pragma unroll
    for (int i = 0; i < 2; i++)
#pragma unroll
        for (int j = 0; j < 8; j++)
#pragma unroll
            for (int q = 0; q < 4; q++) acc[i][j][q] = 0.0f;

    load_chunk(0);
    load_chunk(1);

    for (int c = 0; c < NCH; c++) {
        if (c + 2 < NCH) {
            load_chunk(c + 2);
            asm volatile("cp.async.wait_group 2;" ::: "memory");
        } else if (c + 1 < NCH) {
            asm volatile("cp.async.wait_group 1;" ::: "memory");
        } else {
            asm volatile("cp.async.wait_group 0;" ::: "memory");
        }
        __syncthreads();

        const uint32_t stage = sb + (uint32_t)(c % NSTAGE) * STAGE_BYTES;

        uint32_t ah[2][2][4], bf[2][4][4];
#pragma unroll
        for (int i = 0; i < 2; i++)
            ldsm4(ah[0][i], stage + swa(arow + i * 16, ach));
#pragma unroll
        for (int p = 0; p < 4; p++)
            ldsm4(bf[0][p], stage + TEN_BYTES + swa(brow + p * 16, bch));

#pragma unroll
        for (int s = 0; s < 4; s++) {
            const int cur = s & 1, nxt = cur ^ 1;
            if (s < 3) {
#pragma unroll
                for (int i = 0; i < 2; i++)
                    ldsm4(ah[nxt][i], stage + swa(arow + i * 16, (s + 1) * 2 + ach));
#pragma unroll
                for (int p = 0; p < 4; p++)
                    ldsm4(bf[nxt][p], stage + TEN_BYTES + swa(brow + p * 16, (s + 1) * 2 + bch));
            }
#pragma unroll
            for (int i = 0; i < 2; i++)
#pragma unroll
                for (int j = 0; j < 8; j++) {
                    const int p = j >> 1, hh = (j & 1) * 2;
                    mma16816(acc[i][j], ah[cur][i], bf[cur][p][hh], bf[cur][p][hh + 1]);
                }
        }
        __syncthreads();
    }

    const int rowq = l >> 2, colq = (l & 3) * 2;
#pragma unroll
    for (int j = 0; j < 8; j++) {
        const int ccol = n0 + wn * 64 + j * 8 + colq;
        float b0 = 0.f, b1 = 0.f;
        if (BIAS) { b0 = bias[ccol]; b1 = bias[ccol + 1]; }
#pragma unroll
        for (int i = 0; i < 2; i++) {
            const int r = m0 + wm * 32 + i * 16 + rowq;
            if (OUTH) {
                *(uint32_t*)&Ch[(size_t)r * N + ccol] =
                    pack2(acc[i][j][0], acc[i][j][1]);
                *(uint32_t*)&Ch[(size_t)(r + 8) * N + ccol] =
                    pack2(acc[i][j][2], acc[i][j][3]);
            } else {
                float2 v0 = make_float2(acc[i][j][0] + b0, acc[i][j][1] + b1);
                float2 v1 = make_float2(acc[i][j][2] + b0, acc[i][j][3] + b1);
                *(float2*)&C[(size_t)r * N + ccol]       = v0;
                *(float2*)&C[(size_t)(r + 8) * N + ccol] = v1;
            }
        }
    }
}

// ---------------------------------------------------------------------------
// Tensor-core flash attention (fp16, fp32 softmax), causal.
// CTA = (qtile 128 rows, head, batch), 8 warps (256 thr); warp owns 16 q rows.
// KV tiles of 64 rows, 2-stage cp.async ring.
// smem: Q (16KB) + 2 stages of [K|V] (16KB each) = 48KB.
// ---------------------------------------------------------------------------
#define ATT_SMEM (16384 + 2 * 16384)

__global__ __launch_bounds__(256)
void attn_kernel(const __half* __restrict__ qkvh,
                 __half* __restrict__ yh)
{
    extern __shared__ char smem[];
    const uint32_t sb = smem_u32(smem);
    const int tid = threadIdx.x;
    const int w = tid >> 5, l = tid & 31;
    const int qt = blockIdx.x, h = blockIdx.y, b = blockIdx.z;
    const int q0 = qt * 128;
    const int ktmax = 2 * qt + 1;
    const int tok0 = b * SEQ;
    const int koff = h * HD, qoff = CD + h * HD, voff = 2 * CD + h * HD;

    // Q loader: row tid>>1 (0..127), chunks (tid&1)*4 .. +3
    // KV loader: row tid>>2 (0..63), chunks (tid&3)*2 .. +1 for K and V
    const int qlr = tid >> 1, qlc = (tid & 1) * 4;
    const int klr = tid >> 2, klc = (tid & 3) * 2;

    auto load_kv = [&](int kt) {
        const int k0 = kt * 64;
        const uint32_t base = sb + 16384 + (uint32_t)(kt & 1) * 16384;
        const size_t rowoff = (size_t)(tok0 + k0 + klr) * NQKV;
        const __half* s0 = qkvh + rowoff + koff + klc * 8;
        const __half* s1 = qkvh + rowoff + voff + klc * 8;
#pragma unroll
        for (int c = 0; c < 2; c++) {
            const uint32_t o = swa(klr, klc + c);
            cp16(base + o,        s0 + c * 8);
            cp16(base + 8192 + o, s1 + c * 8);
        }
        asm volatile("cp.async.commit_group;" ::: "memory");
    };

    // prologue: Q tile + kv tile 0 in group0; kv tile 1 in group1
    {
        const size_t rowoff = (size_t)(tok0 + q0 + qlr) * NQKV;
        const __half* s0 = qkvh + rowoff + qoff + qlc * 8;
#pragma unroll
        for (int c = 0; c < 4; c++)
            cp16(sb + swa(qlr, qlc + c), s0 + c * 8);
    }
    load_kv(0);
    load_kv(1);   // ktmax >= 1 always

    const uint32_t qrow = w * 16 + (l & 15);
    const uint32_t qch  = l >> 4;
    const uint32_t krow = (l & 7) + ((l >> 4) << 3);
    const uint32_t kch  = (l >> 3) & 1;
    const uint32_t vrow = (l & 7) + (((l >> 3) & 1) << 3);
    const uint32_t vch  = l >> 4;

    uint32_t qh[4][4];
    float o[8][4];
#pragma unroll
    for (int j = 0; j < 8; j++)
#pragma unroll
        for (int q = 0; q < 4; q++) o[j][q] = 0.0f;
    float sm0 = -1e30f, sm1 = -1e30f, sl0 = 0.0f, sl1 = 0.0f;

    const int r0 = w * 16 + (l >> 2);   // within 128-row q tile
    const int r1 = r0 + 8;
    const float scale = 0.125f;

    for (int kt = 0; kt <= ktmax; kt++) {
        if (kt < ktmax) asm volatile("cp.async.wait_group 1;" ::: "memory");
        else            asm volatile("cp.async.wait_group 0;" ::: "memory");
        __syncthreads();

        if (kt == 0) {
#pragma unroll
            for (int s = 0; s < 4; s++)
                ldsm4(qh[s], sb + swa(qrow, s * 2 + qch));
        }

        const uint32_t stage = sb + 16384 + (uint32_t)(kt & 1) * 16384;

        // ---- S = Q K^T ----
        float sacc[8][4];
#pragma unroll
        for (int j = 0; j < 8; j++)
#pragma unroll
            for (int q = 0; q < 4; q++) sacc[j][q] = 0.0f;

#pragma unroll
        for (int s = 0; s < 4; s++) {
#pragma unroll
            for (int p = 0; p < 4; p++) {
                uint32_t kh[4];
                ldsm4(kh, stage + swa(p * 16 + krow, s * 2 + kch));
#pragma unroll
                for (int jj = 0; jj < 2; jj++)
                    mma16816(sacc[p * 2 + jj], qh[s], kh[jj * 2], kh[jj * 2 + 1]);
            }
        }

        // ---- online softmax (registers only) ----
        // mask needed only for the two diagonal-overlap tiles (kt >= 2*qt)
        const bool mt = (kt >= 2 * qt);
        const int rel = (kt - 2 * qt) * 64;   // col offset minus row base
        float ml0 = -1e30f, ml1 = -1e30f;
#pragma unroll
        for (int j = 0; j < 8; j++) {
            const int c0 = j * 8 + (l & 3) * 2;
            float v0 = sacc[j][0] * scale, v1 = sacc[j][1] * scale;
            float v2 = sacc[j][2] * scale, v3 = sacc[j][3] * scale;
            if (mt) {
                if (rel + c0     > r0) v0 = -1e30f;
                if (rel + c0 + 1 > r0) v1 = -1e30f;
                if (rel + c0     > r1) v2 = -1e30f;
                if (rel + c0 + 1 > r1) v3 = -1e30f;
            }
            sacc[j][0] = v0; sacc[j][1] = v1; sacc[j][2] = v2; sacc[j][3] = v3;
            ml0 = fmaxf(ml0, fmaxf(v0, v1));
            ml1 = fmaxf(ml1, fmaxf(v2, v3));
        }
        ml0 = fmaxf(ml0, __shfl_xor_sync(0xffffffffu, ml0, 1));
        ml0 = fmaxf(ml0, __shfl_xor_sync(0xffffffffu, ml0, 2));
        ml1 = fmaxf(ml1, __shfl_xor_sync(0xffffffffu, ml1, 1));
        ml1 = fmaxf(ml1, __shfl_xor_sync(0xffffffffu, ml1, 2));
        const float mn0 = fmaxf(sm0, ml0), mn1 = fmaxf(sm1, ml1);
        const float cf0 = __expf(sm0 - mn0), cf1 = __expf(sm1 - mn1);
        sm0 = mn0; sm1 = mn1;

        float rs0 = 0.0f, rs1 = 0.0f;
#pragma unroll
        for (int j = 0; j < 8; j++) {
            sacc[j][0] = __expf(sacc[j][0] - mn0);
            sacc[j][1] = __expf(sacc[j][1] - mn0);
            sacc[j][2] = __expf(sacc[j][2] - mn1);
            sacc[j][3] = __expf(sacc[j][3] - mn1);
            rs0 += sacc[j][0] + sacc[j][1];
            rs1 += sacc[j][2] + sacc[j][3];
        }
        rs0 += __shfl_xor_sync(0xffffffffu, rs0, 1);
        rs0 += __shfl_xor_sync(0xffffffffu, rs0, 2);
        rs1 += __shfl_xor_sync(0xffffffffu, rs1, 1);
        rs1 += __shfl_xor_sync(0xffffffffu, rs1, 2);
        sl0 = sl0 * cf0 + rs0;
        sl1 = sl1 * cf1 + rs1;

#pragma unroll
        for (int j = 0; j < 8; j++) {
            o[j][0] *= cf0; o[j][1] *= cf0;
            o[j][2] *= cf1; o[j][3] *= cf1;
        }

        // ---- P fragments (acc layout == A-fragment layout) ----
        uint32_t ph[4][4];
#pragma unroll
        for (int t = 0; t < 4; t++) {
            ph[t][0] = pack2(sacc[2 * t][0],     sacc[2 * t][1]);
            ph[t][1] = pack2(sacc[2 * t][2],     sacc[2 * t][3]);
            ph[t][2] = pack2(sacc[2 * t + 1][0], sacc[2 * t + 1][1]);
            ph[t][3] = pack2(sacc[2 * t + 1][2], sacc[2 * t + 1][3]);
        }

        // ---- O += P V, V^T via ldmatrix.trans ----
#pragma unroll
        for (int t = 0; t < 4; t++) {
#pragma unroll
            for (int p = 0; p < 4; p++) {
                uint32_t vh[4];
                ldsm4t(vh, stage + 8192 + swa(t * 16 + vrow, p * 2 + vch));
#pragma unroll
                for (int jj = 0; jj < 2; jj++)
                    mma16816(o[p * 2 + jj], ph[t], vh[jj * 2], vh[jj * 2 + 1]);
            }
        }

        __syncthreads();
        if (kt + 2 <= ktmax) load_kv(kt + 2);
    }

    // ---- finalize: divide by l, store fp16 ----
    const float inv0 = 1.0f / sl0, inv1 = 1.0f / sl1;
    const size_t row0 = (size_t)(tok0 + q0 + r0) * CD + h * HD;
    const size_t row1 = (size_t)(tok0 + q0 + r1) * CD + h * HD;
#pragma unroll
    for (int j = 0; j < 8; j++) {
        const int c0 = j * 8 + (l & 3) * 2;
        *(uint32_t*)&yh[row0 + c0] = pack2(o[j][0] * inv0, o[j][1] * inv0);
        *(uint32_t*)&yh[row1 + c0] = pack2(o[j][2] * inv1, o[j][3] * inv1);
    }
}

// ---------------------------------------------------------------------------
extern "C" void kernel_launch(void* const* d_in, const int* in_sizes, int n_in,
                              void* d_out, int out_size)
{
    const float* x      = (const float*)d_in[0];
    const float* w_attn = (const float*)d_in[1];
    const float* w_proj = (const float*)d_in[2];
    const float* b_proj = (const float*)d_in[3];
    float* out = (float*)d_out;

    __half *xh, *wah, *wph, *qkvh, *yh;
    cudaGetSymbolAddress((void**)&xh,   g_xh);
    cudaGetSymbolAddress((void**)&wah,  g_wah);
    cudaGetSymbolAddress((void**)&wph,  g_wph);
    cudaGetSymbolAddress((void**)&qkvh, g_qkvh);
    cudaGetSymbolAddress((void**)&yh,   g_yh);

    cudaFuncSetAttribute(attn_kernel,
                         cudaFuncAttributeMaxDynamicSharedMemorySize, ATT_SMEM);
    cudaFuncSetAttribute(gemm_f16<false, true>,
                         cudaFuncAttributeMaxDynamicSharedMemorySize, GEMM_SMEM);
    cudaFuncSetAttribute(gemm_f16<true, false>,
                         cudaFuncAttributeMaxDynamicSharedMemorySize, GEMM_SMEM);

    // 0) convert inputs to fp16
    cvt_f16<<<(MTOK * CD / 4 + 255) / 256, 256>>>(x, xh, MTOK * CD);
    cvt_f16<<<(NQKV * CD / 4 + 255) / 256, 256>>>(w_attn, wah, NQKV * CD);
    cvt_f16<<<(CD * CD / 4 + 255) / 256, 256>>>(w_proj, wph, CD * CD);

    // 1) QKV projection -> qkv fp16
    gemm_f16<false, true><<<dim3(NQKV / 128, MTOK / 128), 256, GEMM_SMEM>>>(
        xh, wah, nullptr, nullptr, qkvh, MTOK, NQKV, CD);

    // 2) tensor-core causal flash attention -> y fp16
    attn_kernel<<<dim3(SEQ / 128, NH, BATCH), 256, ATT_SMEM>>>(qkvh, yh);

    // 3) output projection: out = y @ w_proj^T + b_proj (fp32 out)
    gemm_f16<true, false><<<dim3(CD / 128, MTOK / 128), 256, GEMM_SMEM>>>(
        yh, wph, b_proj, out, nullptr, MTOK, CD, CD);
}

// round 8
// speedup vs baseline: 5.1541x; 1.0393x over previous
#include <cuda_runtime.h>
#include <cuda_fp16.h>
#include <cstdint>

// Problem constants
#define BATCH 8
#define SEQ   1024
#define CD    1024
#define NH    16
#define HD    64
#define MTOK  (BATCH * SEQ)      // 8192 tokens
#define NQKV  (3 * CD)           // 3072

// Scratch (no allocations allowed -> __device__ globals)
__device__ __half g_xh[MTOK * CD];
__device__ __half g_wah[NQKV * CD];
__device__ __half g_wph[CD * CD];
__device__ __half g_qkvh[MTOK * NQKV];
__device__ __half g_yh[MTOK * CD];

// ---------------------------------------------------------------------------
// PTX helpers (portable sm_80+ tensor path: cp.async + ldmatrix + mma.sync)
// ---------------------------------------------------------------------------
__device__ __forceinline__ uint32_t smem_u32(const void* p) {
    return (uint32_t)__cvta_generic_to_shared(p);
}
__device__ __forceinline__ void cp16(uint32_t dst_smem, const void* src) {
    asm volatile("cp.async.cg.shared.global [%0], [%1], 16;"
                 :: "r"(dst_smem), "l"(__cvta_generic_to_global(src)) : "memory");
}
__device__ __forceinline__ void ldsm4(uint32_t* r, uint32_t addr) {
    asm volatile("ldmatrix.sync.aligned.m8n8.x4.shared.b16 {%0,%1,%2,%3}, [%4];"
                 : "=r"(r[0]), "=r"(r[1]), "=r"(r[2]), "=r"(r[3]) : "r"(addr));
}
__device__ __forceinline__ void ldsm4t(uint32_t* r, uint32_t addr) {
    asm volatile("ldmatrix.sync.aligned.m8n8.x4.trans.shared.b16 {%0,%1,%2,%3}, [%4];"
                 : "=r"(r[0]), "=r"(r[1]), "=r"(r[2]), "=r"(r[3]) : "r"(addr));
}
__device__ __forceinline__ void mma16816(float* d, const uint32_t* a,
                                         uint32_t b0, uint32_t b1) {
    asm volatile(
        "mma.sync.aligned.m16n8k16.row.col.f32.f16.f16.f32 "
        "{%0,%1,%2,%3}, {%4,%5,%6,%7}, {%8,%9}, {%0,%1,%2,%3};"
        : "+f"(d[0]), "+f"(d[1]), "+f"(d[2]), "+f"(d[3])
        : "r"(a[0]), "r"(a[1]), "r"(a[2]), "r"(a[3]), "r"(b0), "r"(b1));
}
__device__ __forceinline__ uint32_t pack2(float a, float b) {
    __half2 h = __floats2half2_rn(a, b);
    return *(uint32_t*)&h;
}

// 128B-row swizzle: 16B chunk ch (0..7) of row r
__device__ __forceinline__ uint32_t swa(uint32_t r, uint32_t ch) {
    return r * 128u + (((ch) ^ (r & 7u)) << 4);
}

// ---------------------------------------------------------------------------
// fp32 -> fp16 convert, 4 elements per thread
// ---------------------------------------------------------------------------
__global__ __launch_bounds__(256)
void cvt_f16(const float* __restrict__ in, __half* __restrict__ out, int n)
{
    int i = (blockIdx.x * blockDim.x + threadIdx.x) * 4;
    if (i >= n) return;
    float4 v = *(const float4*)(in + i);
    *(uint32_t*)(out + i)     = pack2(v.x, v.y);
    *(uint32_t*)(out + i + 2) = pack2(v.z, v.w);
}

// ---------------------------------------------------------------------------
// fp16 mma.sync GEMM: C[m,n] = sum_k A[m,k] * B[n,k]  (+bias)
// 64x128 CTA tile, 4 warps (32m x 64n each), BK=64, 2-stage cp.async pipe.
// Small CTAs -> 4 independent barrier domains per SM (de-phased pipelines).
// ---------------------------------------------------------------------------
#define A_BYTES 8192                    // 64 rows x 128B
#define B_BYTES 16384                   // 128 rows x 128B
#define STAGE_BYTES (A_BYTES + B_BYTES) // 24 KB
#define NSTAGE 2
#define GEMM_SMEM (NSTAGE * STAGE_BYTES)  // 48 KB

template <bool BIAS, bool OUTH>
__global__ __launch_bounds__(128, 4)
void gemm_f16(const __half* __restrict__ A, const __half* __restrict__ B,
              const float* __restrict__ bias, float* __restrict__ C,
              __half* __restrict__ Ch, int M, int N, int K)
{
    extern __shared__ char smem[];
    const uint32_t sb = smem_u32(smem);
    const int tid = threadIdx.x;
    const int wid = tid >> 5, l = tid & 31;
    const int m0 = blockIdx.y * 64, n0 = blockIdx.x * 128;
    const int NCH = K >> 6;            // BK=64

    // loader: A rows via pairs (2 threads/row, 4 chunks each), B rows 1:1.
    const int alr = tid >> 1, alc = (tid & 1) * 4;   // A row 0..63, chunk base
    const __half* agp = A + (size_t)(m0 + alr) * K + alc * 8;
    const __half* bgp = B + (size_t)(n0 + tid) * K;

    auto load_chunk = [&](int c) {
        const uint32_t stage = sb + (uint32_t)(c & 1) * STAGE_BYTES;
        const int k0 = c << 6;
#pragma unroll
        for (int ch = 0; ch < 4; ch++)
            cp16(stage + swa(alr, alc + ch), agp + k0 + ch * 8);
#pragma unroll
        for (int ch = 0; ch < 8; ch++)
            cp16(stage + A_BYTES + swa(tid, ch), bgp + k0 + ch * 8);
        asm volatile("cp.async.commit_group;" ::: "memory");
    };

    const int wm = wid >> 1, wn = wid & 1;

    const uint32_t arow = wm * 32 + (l & 15);
    const uint32_t ach  = l >> 4;
    const uint32_t brow = wn * 64 + (l & 7) + ((l >> 4) << 3);
    const uint32_t bch  = (l >> 3) & 1;

    float acc[2][8][4];
#pragma unroll
    for (int i = 0; i < 2; i++)
#pragma unroll
        for (int j = 0; j < 8; j++)
#pragma unroll
            for (int q = 0; q < 4; q++) acc[i][j][q] = 0.0f;

    load_chunk(0);
    load_chunk(1);

    for (int c = 0; c < NCH; c++) {
        if (c + 1 < NCH) asm volatile("cp.async.wait_group 1;" ::: "memory");
        else             asm volatile("cp.async.wait_group 0;" ::: "memory");
        __syncthreads();

        const uint32_t stage = sb + (uint32_t)(c & 1) * STAGE_BYTES;
#pragma unroll
        for (int s = 0; s < 4; s++) {
            uint32_t ah[2][4];
#pragma unroll
            for (int i = 0; i < 2; i++)
                ldsm4(ah[i], stage + swa(arow + i * 16, s * 2 + ach));
            uint32_t bf[4][4];
#pragma unroll
            for (int p = 0; p < 4; p++)
                ldsm4(bf[p], stage + A_BYTES + swa(brow + p * 16, s * 2 + bch));
#pragma unroll
            for (int i = 0; i < 2; i++)
#pragma unroll
                for (int j = 0; j < 8; j++) {
                    const int p = j >> 1, hh = (j & 1) * 2;
                    mma16816(acc[i][j], ah[i], bf[p][hh], bf[p][hh + 1]);
                }
        }
        __syncthreads();
        if (c + 2 < NCH) load_chunk(c + 2);
    }

    const int rowq = l >> 2, colq = (l & 3) * 2;
#pragma unroll
    for (int j = 0; j < 8; j++) {
        const int ccol = n0 + wn * 64 + j * 8 + colq;
        float b0 = 0.f, b1 = 0.f;
        if (BIAS) { b0 = bias[ccol]; b1 = bias[ccol + 1]; }
#pragma unroll
        for (int i = 0; i < 2; i++) {
            const int r = m0 + wm * 32 + i * 16 + rowq;
            if (OUTH) {
                *(uint32_t*)&Ch[(size_t)r * N + ccol] =
                    pack2(acc[i][j][0], acc[i][j][1]);
                *(uint32_t*)&Ch[(size_t)(r + 8) * N + ccol] =
                    pack2(acc[i][j][2], acc[i][j][3]);
            } else {
                float2 v0 = make_float2(acc[i][j][0] + b0, acc[i][j][1] + b1);
                float2 v1 = make_float2(acc[i][j][2] + b0, acc[i][j][3] + b1);
                *(float2*)&C[(size_t)r * N + ccol]       = v0;
                *(float2*)&C[(size_t)(r + 8) * N + ccol] = v1;
            }
        }
    }
}

// ---------------------------------------------------------------------------
// Tensor-core flash attention (fp16, fp32 softmax), causal.
// CTA = (qtile 128 rows, head, batch), 8 warps (256 thr); warp owns 16 q rows.
// KV tiles of 64 rows, 2-stage cp.async ring.
// smem: Q (16KB) + 2 stages of [K|V] (16KB each) = 48KB.
// ---------------------------------------------------------------------------
#define ATT_SMEM (16384 + 2 * 16384)

__global__ __launch_bounds__(256)
void attn_kernel(const __half* __restrict__ qkvh,
                 __half* __restrict__ yh)
{
    extern __shared__ char smem[];
    const uint32_t sb = smem_u32(smem);
    const int tid = threadIdx.x;
    const int w = tid >> 5, l = tid & 31;
    const int qt = blockIdx.x, h = blockIdx.y, b = blockIdx.z;
    const int q0 = qt * 128;
    const int ktmax = 2 * qt + 1;
    const int tok0 = b * SEQ;
    const int koff = h * HD, qoff = CD + h * HD, voff = 2 * CD + h * HD;

    const int qlr = tid >> 1, qlc = (tid & 1) * 4;
    const int klr = tid >> 2, klc = (tid & 3) * 2;

    auto load_kv = [&](int kt) {
        const int k0 = kt * 64;
        const uint32_t base = sb + 16384 + (uint32_t)(kt & 1) * 16384;
        const size_t rowoff = (size_t)(tok0 + k0 + klr) * NQKV;
        const __half* s0 = qkvh + rowoff + koff + klc * 8;
        const __half* s1 = qkvh + rowoff + voff + klc * 8;
#pragma unroll
        for (int c = 0; c < 2; c++) {
            const uint32_t o = swa(klr, klc + c);
            cp16(base + o,        s0 + c * 8);
            cp16(base + 8192 + o, s1 + c * 8);
        }
        asm volatile("cp.async.commit_group;" ::: "memory");
    };

    {
        const size_t rowoff = (size_t)(tok0 + q0 + qlr) * NQKV;
        const __half* s0 = qkvh + rowoff + qoff + qlc * 8;
#pragma unroll
        for (int c = 0; c < 4; c++)
            cp16(sb + swa(qlr, qlc + c), s0 + c * 8);
    }
    load_kv(0);
    load_kv(1);

    const uint32_t qrow = w * 16 + (l & 15);
    const uint32_t qch  = l >> 4;
    const uint32_t krow = (l & 7) + ((l >> 4) << 3);
    const uint32_t kch  = (l >> 3) & 1;
    const uint32_t vrow = (l & 7) + (((l >> 3) & 1) << 3);
    const uint32_t vch  = l >> 4;

    uint32_t qh[4][4];
    float o[8][4];
#pragma unroll
    for (int j = 0; j < 8; j++)
#pragma unroll
        for (int q = 0; q < 4; q++) o[j][q] = 0.0f;
    float sm0 = -1e30f, sm1 = -1e30f, sl0 = 0.0f, sl1 = 0.0f;

    const int r0 = w * 16 + (l >> 2);
    const int r1 = r0 + 8;
    const float scale = 0.125f;

    for (int kt = 0; kt <= ktmax; kt++) {
        if (kt < ktmax) asm volatile("cp.async.wait_group 1;" ::: "memory");
        else            asm volatile("cp.async.wait_group 0;" ::: "memory");
        __syncthreads();

        if (kt == 0) {
#pragma unroll
            for (int s = 0; s < 4; s++)
                ldsm4(qh[s], sb + swa(qrow, s * 2 + qch));
        }

        const uint32_t stage = sb + 16384 + (uint32_t)(kt & 1) * 16384;

        float sacc[8][4];
#pragma unroll
        for (int j = 0; j < 8; j++)
#pragma unroll
            for (int q = 0; q < 4; q++) sacc[j][q] = 0.0f;

#pragma unroll
        for (int s = 0; s < 4; s++) {
#pragma unroll
            for (int p = 0; p < 4; p++) {
                uint32_t kh[4];
                ldsm4(kh, stage + swa(p * 16 + krow, s * 2 + kch));
#pragma unroll
                for (int jj = 0; jj < 2; jj++)
                    mma16816(sacc[p * 2 + jj], qh[s], kh[jj * 2], kh[jj * 2 + 1]);
            }
        }

        const bool mt = (kt >= 2 * qt);
        const int rel = (kt - 2 * qt) * 64;
        float ml0 = -1e30f, ml1 = -1e30f;
#pragma unroll
        for (int j = 0; j < 8; j++) {
            const int c0 = j * 8 + (l & 3) * 2;
            float v0 = sacc[j][0] * scale, v1 = sacc[j][1] * scale;
            float v2 = sacc[j][2] * scale, v3 = sacc[j][3] * scale;
            if (mt) {
                if (rel + c0     > r0) v0 = -1e30f;
                if (rel + c0 + 1 > r0) v1 = -1e30f;
                if (rel + c0     > r1) v2 = -1e30f;
                if (rel + c0 + 1 > r1) v3 = -1e30f;
            }
            sacc[j][0] = v0; sacc[j][1] = v1; sacc[j][2] = v2; sacc[j][3] = v3;
            ml0 = fmaxf(ml0, fmaxf(v0, v1));
            ml1 = fmaxf(ml1, fmaxf(v2, v3));
        }
        ml0 = fmaxf(ml0, __shfl_xor_sync(0xffffffffu, ml0, 1));
        ml0 = fmaxf(ml0, __shfl_xor_sync(0xffffffffu, ml0, 2));
        ml1 = fmaxf(ml1, __shfl_xor_sync(0xffffffffu, ml1, 1));
        ml1 = fmaxf(ml1, __shfl_xor_sync(0xffffffffu, ml1, 2));
        const float mn0 = fmaxf(sm0, ml0), mn1 = fmaxf(sm1, ml1);
        const float cf0 = __expf(sm0 - mn0), cf1 = __expf(sm1 - mn1);
        sm0 = mn0; sm1 = mn1;

        float rs0 = 0.0f, rs1 = 0.0f;
#pragma unroll
        for (int j = 0; j < 8; j++) {
            sacc[j][0] = __expf(sacc[j][0] - mn0);
            sacc[j][1] = __expf(sacc[j][1] - mn0);
            sacc[j][2] = __expf(sacc[j][2] - mn1);
            sacc[j][3] = __expf(sacc[j][3] - mn1);
            rs0 += sacc[j][0] + sacc[j][1];
            rs1 += sacc[j][2] + sacc[j][3];
        }
        rs0 += __shfl_xor_sync(0xffffffffu, rs0, 1);
        rs0 += __shfl_xor_sync(0xffffffffu, rs0, 2);
        rs1 += __shfl_xor_sync(0xffffffffu, rs1, 1);
        rs1 += __shfl_xor_sync(0xffffffffu, rs1, 2);
        sl0 = sl0 * cf0 + rs0;
        sl1 = sl1 * cf1 + rs1;

#pragma unroll
        for (int j = 0; j < 8; j++) {
            o[j][0] *= cf0; o[j][1] *= cf0;
            o[j][2] *= cf1; o[j][3] *= cf1;
        }

        uint32_t ph[4][4];
#pragma unroll
        for (int t = 0; t < 4; t++) {
            ph[t][0] = pack2(sacc[2 * t][0],     sacc[2 * t][1]);
            ph[t][1] = pack2(sacc[2 * t][2],     sacc[2 * t][3]);
            ph[t][2] = pack2(sacc[2 * t + 1][0], sacc[2 * t + 1][1]);
            ph[t][3] = pack2(sacc[2 * t + 1][2], sacc[2 * t + 1][3]);
        }

#pragma unroll
        for (int t = 0; t < 4; t++) {
#pragma unroll
            for (int p = 0; p < 4; p++) {
                uint32_t vh[4];
                ldsm4t(vh, stage + 8192 + swa(t * 16 + vrow, p * 2 + vch));
#pragma unroll
                for (int jj = 0; jj < 2; jj++)
                    mma16816(o[p * 2 + jj], ph[t], vh[jj * 2], vh[jj * 2 + 1]);
            }
        }

        __syncthreads();
        if (kt + 2 <= ktmax) load_kv(kt + 2);
    }

    const float inv0 = 1.0f / sl0, inv1 = 1.0f / sl1;
    const size_t row0 = (size_t)(tok0 + q0 + r0) * CD + h * HD;
    const size_t row1 = (size_t)(tok0 + q0 + r1) * CD + h * HD;
#pragma unroll
    for (int j = 0; j < 8; j++) {
        const int c0 = j * 8 + (l & 3) * 2;
        *(uint32_t*)&yh[row0 + c0] = pack2(o[j][0] * inv0, o[j][1] * inv0);
        *(uint32_t*)&yh[row1 + c0] = pack2(o[j][2] * inv1, o[j][3] * inv1);
    }
}

// ---------------------------------------------------------------------------
extern "C" void kernel_launch(void* const* d_in, const int* in_sizes, int n_in,
                              void* d_out, int out_size)
{
    const float* x      = (const float*)d_in[0];
    const float* w_attn = (const float*)d_in[1];
    const float* w_proj = (const float*)d_in[2];
    const float* b_proj = (const float*)d_in[3];
    float* out = (float*)d_out;

    __half *xh, *wah, *wph, *qkvh, *yh;
    cudaGetSymbolAddress((void**)&xh,   g_xh);
    cudaGetSymbolAddress((void**)&wah,  g_wah);
    cudaGetSymbolAddress((void**)&wph,  g_wph);
    cudaGetSymbolAddress((void**)&qkvh, g_qkvh);
    cudaGetSymbolAddress((void**)&yh,   g_yh);

    cudaFuncSetAttribute(attn_kernel,
                         cudaFuncAttributeMaxDynamicSharedMemorySize, ATT_SMEM);
    cudaFuncSetAttribute(gemm_f16<false, true>,
                         cudaFuncAttributeMaxDynamicSharedMemorySize, GEMM_SMEM);
    cudaFuncSetAttribute(gemm_f16<true, false>,
                         cudaFuncAttributeMaxDynamicSharedMemorySize, GEMM_SMEM);

    // 0) convert inputs to fp16
    cvt_f16<<<(MTOK * CD / 4 + 255) / 256, 256>>>(x, xh, MTOK * CD);
    cvt_f16<<<(NQKV * CD / 4 + 255) / 256, 256>>>(w_attn, wah, NQKV * CD);
    cvt_f16<<<(CD * CD / 4 + 255) / 256, 256>>>(w_proj, wph, CD * CD);

    // 1) QKV projection -> qkv fp16
    gemm_f16<false, true><<<dim3(NQKV / 128, MTOK / 64), 128, GEMM_SMEM>>>(
        xh, wah, nullptr, nullptr, qkvh, MTOK, NQKV, CD);

    // 2) tensor-core causal flash attention -> y fp16
    attn_kernel<<<dim3(SEQ / 128, NH, BATCH), 256, ATT_SMEM>>>(qkvh, yh);

    // 3) output projection: out = y @ w_proj^T + b_proj (fp32 out)
    gemm_f16<true, false><<<dim3(CD / 128, MTOK / 64), 128, GEMM_SMEM>>>(
        yh, wph, b_proj, out, nullptr, MTOK, CD, CD);
}

// round 10
// speedup vs baseline: 5.1976x; 1.0084x over previous
#include <cuda_runtime.h>
#include <cuda_fp16.h>
#include <cstdint>

// Problem constants
#define BATCH 8
#define SEQ   1024
#define CD    1024
#define NH    16
#define HD    64
#define MTOK  (BATCH * SEQ)      // 8192 tokens
#define NQKV  (3 * CD)           // 3072

// Scratch (no allocations allowed -> __device__ globals)
__device__ __half g_xh[MTOK * CD];
__device__ __half g_wah[NQKV * CD];
__device__ __half g_wph[CD * CD];
__device__ __half g_qkvh[MTOK * NQKV];
__device__ __half g_yh[MTOK * CD];

// ---------------------------------------------------------------------------
// PTX helpers (portable sm_80+ tensor path: cp.async + ldmatrix + mma.sync)
// ---------------------------------------------------------------------------
__device__ __forceinline__ uint32_t smem_u32(const void* p) {
    return (uint32_t)__cvta_generic_to_shared(p);
}
__device__ __forceinline__ void cp16(uint32_t dst_smem, const void* src) {
    asm volatile("cp.async.cg.shared.global [%0], [%1], 16;"
                 :: "r"(dst_smem), "l"(__cvta_generic_to_global(src)) : "memory");
}
__device__ __forceinline__ void ldsm4(uint32_t* r, uint32_t addr) {
    asm volatile("ldmatrix.sync.aligned.m8n8.x4.shared.b16 {%0,%1,%2,%3}, [%4];"
                 : "=r"(r[0]), "=r"(r[1]), "=r"(r[2]), "=r"(r[3]) : "r"(addr));
}
__device__ __forceinline__ void ldsm4t(uint32_t* r, uint32_t addr) {
    asm volatile("ldmatrix.sync.aligned.m8n8.x4.trans.shared.b16 {%0,%1,%2,%3}, [%4];"
                 : "=r"(r[0]), "=r"(r[1]), "=r"(r[2]), "=r"(r[3]) : "r"(addr));
}
__device__ __forceinline__ void mma16816(float* d, const uint32_t* a,
                                         uint32_t b0, uint32_t b1) {
    asm volatile(
        "mma.sync.aligned.m16n8k16.row.col.f32.f16.f16.f32 "
        "{%0,%1,%2,%3}, {%4,%5,%6,%7}, {%8,%9}, {%0,%1,%2,%3};"
        : "+f"(d[0]), "+f"(d[1]), "+f"(d[2]), "+f"(d[3])
        : "r"(a[0]), "r"(a[1]), "r"(a[2]), "r"(a[3]), "r"(b0), "r"(b1));
}
__device__ __forceinline__ uint32_t pack2(float a, float b) {
    __half2 h = __floats2half2_rn(a, b);
    return *(uint32_t*)&h;
}

// 128B-row swizzle: 16B chunk ch (0..7) of row r
__device__ __forceinline__ uint32_t swa(uint32_t r, uint32_t ch) {
    return r * 128u + (((ch) ^ (r & 7u)) << 4);
}

// ---------------------------------------------------------------------------
// fp32 -> fp16 convert, 4 elements per thread
// ---------------------------------------------------------------------------
__global__ __launch_bounds__(256)
void cvt_f16(const float* __restrict__ in, __half* __restrict__ out, int n)
{
    int i = (blockIdx.x * blockDim.x + threadIdx.x) * 4;
    if (i >= n) return;
    float4 v = *(const float4*)(in + i);
    *(uint32_t*)(out + i)     = pack2(v.x, v.y);
    *(uint32_t*)(out + i + 2) = pack2(v.z, v.w);
}

// ---------------------------------------------------------------------------
// fp16 mma.sync GEMM: C[m,n] = sum_k A[m,k] * B[n,k]  (+bias)
// 128x128 CTA tile, 4 warps, each 64x64 (HMMA:LDSM ratio 4.0), BK=64,
// 2-stage cp.async pipe, 2 CTAs/SM with 256-reg budget.
// ---------------------------------------------------------------------------
#define TILE_BYTES 16384                // 128 rows x 128B
#define STAGE_BYTES (2 * TILE_BYTES)    // A + B = 32 KB
#define NSTAGE 2
#define GEMM_SMEM (NSTAGE * STAGE_BYTES)  // 64 KB

template <bool BIAS, bool OUTH>
__global__ __launch_bounds__(128, 2)
void gemm_f16(const __half* __restrict__ A, const __half* __restrict__ B,
              const float* __restrict__ bias, float* __restrict__ C,
              __half* __restrict__ Ch, int M, int N, int K)
{
    extern __shared__ char smem[];
    const uint32_t sb = smem_u32(smem);
    const int tid = threadIdx.x;
    const int wid = tid >> 5, l = tid & 31;
    const int m0 = blockIdx.y * 128, n0 = blockIdx.x * 128;
    const int NCH = K >> 6;            // BK=64

    // loader: each thread owns one 128B row of A and one of B (8 cp16 each)
    const __half* agp = A + (size_t)(m0 + tid) * K;
    const __half* bgp = B + (size_t)(n0 + tid) * K;

    auto load_chunk = [&](int c) {
        const uint32_t stage = sb + (uint32_t)(c & 1) * STAGE_BYTES;
        const int k0 = c << 6;
#pragma unroll
        for (int ch = 0; ch < 8; ch++)
            cp16(stage + swa(tid, ch), agp + k0 + ch * 8);
#pragma unroll
        for (int ch = 0; ch < 8; ch++)
            cp16(stage + TILE_BYTES + swa(tid, ch), bgp + k0 + ch * 8);
        asm volatile("cp.async.commit_group;" ::: "memory");
    };

    // warp tile: 64m x 64n; wm,wn in {0,1}
    const int wm = wid >> 1, wn = wid & 1;

    const uint32_t arow = wm * 64 + (l & 15);
    const uint32_t ach  = l >> 4;
    const uint32_t brow = wn * 64 + (l & 7) + ((l >> 4) << 3);
    const uint32_t bch  = (l >> 3) & 1;

    float acc[4][8][4];
#pragma unroll
    for (int i = 0; i < 4; i++)
#pragma unroll
        for (int j = 0; j < 8; j++)
#pragma unroll
            for (int q = 0; q < 4; q++) acc[i][j][q] = 0.0f;

    load_chunk(0);
    load_chunk(1);

    for (int c = 0; c < NCH; c++) {
        if (c + 1 < NCH) asm volatile("cp.async.wait_group 1;" ::: "memory");
        else             asm volatile("cp.async.wait_group 0;" ::: "memory");
        __syncthreads();

        const uint32_t stage = sb + (uint32_t)(c & 1) * STAGE_BYTES;
#pragma unroll
        for (int s = 0; s < 4; s++) {
            uint32_t ah[4][4];
#pragma unroll
            for (int i = 0; i < 4; i++)
                ldsm4(ah[i], stage + swa(arow + i * 16, s * 2 + ach));
            uint32_t bf[4][4];
#pragma unroll
            for (int p = 0; p < 4; p++)
                ldsm4(bf[p], stage + TILE_BYTES + swa(brow + p * 16, s * 2 + bch));
#pragma unroll
            for (int i = 0; i < 4; i++)
#pragma unroll
                for (int j = 0; j < 8; j++) {
                    const int p = j >> 1, hh = (j & 1) * 2;
                    mma16816(acc[i][j], ah[i], bf[p][hh], bf[p][hh + 1]);
                }
        }
        __syncthreads();
        if (c + 2 < NCH) load_chunk(c + 2);
    }

    const int rowq = l >> 2, colq = (l & 3) * 2;
#pragma unroll
    for (int j = 0; j < 8; j++) {
        const int ccol = n0 + wn * 64 + j * 8 + colq;
        float b0 = 0.f, b1 = 0.f;
        if (BIAS) { b0 = bias[ccol]; b1 = bias[ccol + 1]; }
#pragma unroll
        for (int i = 0; i < 4; i++) {
            const int r = m0 + wm * 64 + i * 16 + rowq;
            if (OUTH) {
                *(uint32_t*)&Ch[(size_t)r * N + ccol] =
                    pack2(acc[i][j][0], acc[i][j][1]);
                *(uint32_t*)&Ch[(size_t)(r + 8) * N + ccol] =
                    pack2(acc[i][j][2], acc[i][j][3]);
            } else {
                float2 v0 = make_float2(acc[i][j][0] + b0, acc[i][j][1] + b1);
                float2 v1 = make_float2(acc[i][j][2] + b0, acc[i][j][3] + b1);
                *(float2*)&C[(size_t)r * N + ccol]       = v0;
                *(float2*)&C[(size_t)(r + 8) * N + ccol] = v1;
            }
        }
    }
}

// ---------------------------------------------------------------------------
// Tensor-core flash attention (fp16, fp32 softmax), causal. (unchanged)
// CTA = (qtile 128 rows, head, batch), 8 warps (256 thr); warp owns 16 q rows.
// KV tiles of 64 rows, 2-stage cp.async ring.
// smem: Q (16KB) + 2 stages of [K|V] (16KB each) = 48KB.
// ---------------------------------------------------------------------------
#define ATT_SMEM (16384 + 2 * 16384)

__global__ __launch_bounds__(256)
void attn_kernel(const __half* __restrict__ qkvh,
                 __half* __restrict__ yh)
{
    extern __shared__ char smem[];
    const uint32_t sb = smem_u32(smem);
    const int tid = threadIdx.x;
    const int w = tid >> 5, l = tid & 31;
    const int qt = blockIdx.x, h = blockIdx.y, b = blockIdx.z;
    const int q0 = qt * 128;
    const int ktmax = 2 * qt + 1;
    const int tok0 = b * SEQ;
    const int koff = h * HD, qoff = CD + h * HD, voff = 2 * CD + h * HD;

    const int qlr = tid >> 1, qlc = (tid & 1) * 4;
    const int klr = tid >> 2, klc = (tid & 3) * 2;

    auto load_kv = [&](int kt) {
        const int k0 = kt * 64;
        const uint32_t base = sb + 16384 + (uint32_t)(kt & 1) * 16384;
        const size_t rowoff = (size_t)(tok0 + k0 + klr) * NQKV;
        const __half* s0 = qkvh + rowoff + koff + klc * 8;
        const __half* s1 = qkvh + rowoff + voff + klc * 8;
#pragma unroll
        for (int c = 0; c < 2; c++) {
            const uint32_t o = swa(klr, klc + c);
            cp16(base + o,        s0 + c * 8);
            cp16(base + 8192 + o, s1 + c * 8);
        }
        asm volatile("cp.async.commit_group;" ::: "memory");
    };

    {
        const size_t rowoff = (size_t)(tok0 + q0 + qlr) * NQKV;
        const __half* s0 = qkvh + rowoff + qoff + qlc * 8;
#pragma unroll
        for (int c = 0; c < 4; c++)
            cp16(sb + swa(qlr, qlc + c), s0 + c * 8);
    }
    load_kv(0);
    load_kv(1);

    const uint32_t qrow = w * 16 + (l & 15);
    const uint32_t qch  = l >> 4;
    const uint32_t krow = (l & 7) + ((l >> 4) << 3);
    const uint32_t kch  = (l >> 3) & 1;
    const uint32_t vrow = (l & 7) + (((l >> 3) & 1) << 3);
    const uint32_t vch  = l >> 4;

    uint32_t qh[4][4];
    float o[8][4];
#pragma unroll
    for (int j = 0; j < 8; j++)
#pragma unroll
        for (int q = 0; q < 4; q++) o[j][q] = 0.0f;
    float sm0 = -1e30f, sm1 = -1e30f, sl0 = 0.0f, sl1 = 0.0f;

    const int r0 = w * 16 + (l >> 2);
    const int r1 = r0 + 8;
    const float scale = 0.125f;

    for (int kt = 0; kt <= ktmax; kt++) {
        if (kt < ktmax) asm volatile("cp.async.wait_group 1;" ::: "memory");
        else            asm volatile("cp.async.wait_group 0;" ::: "memory");
        __syncthreads();

        if (kt == 0) {
#pragma unroll
            for (int s = 0; s < 4; s++)
                ldsm4(qh[s], sb + swa(qrow, s * 2 + qch));
        }

        const uint32_t stage = sb + 16384 + (uint32_t)(kt & 1) * 16384;

        float sacc[8][4];
#pragma unroll
        for (int j = 0; j < 8; j++)
#pragma unroll
            for (int q = 0; q < 4; q++) sacc[j][q] = 0.0f;

#pragma unroll
        for (int s = 0; s < 4; s++) {
#pragma unroll
            for (int p = 0; p < 4; p++) {
                uint32_t kh[4];
                ldsm4(kh, stage + swa(p * 16 + krow, s * 2 + kch));
#pragma unroll
                for (int jj = 0; jj < 2; jj++)
                    mma16816(sacc[p * 2 + jj], qh[s], kh[jj * 2], kh[jj * 2 + 1]);
            }
        }

        const bool mt = (kt >= 2 * qt);
        const int rel = (kt - 2 * qt) * 64;
        float ml0 = -1e30f, ml1 = -1e30f;
#pragma unroll
        for (int j = 0; j < 8; j++) {
            const int c0 = j * 8 + (l & 3) * 2;
            float v0 = sacc[j][0] * scale, v1 = sacc[j][1] * scale;
            float v2 = sacc[j][2] * scale, v3 = sacc[j][3] * scale;
            if (mt) {
                if (rel + c0     > r0) v0 = -1e30f;
                if (rel + c0 + 1 > r0) v1 = -1e30f;
                if (rel + c0     > r1) v2 = -1e30f;
                if (rel + c0 + 1 > r1) v3 = -1e30f;
            }
            sacc[j][0] = v0; sacc[j][1] = v1; sacc[j][2] = v2; sacc[j][3] = v3;
            ml0 = fmaxf(ml0, fmaxf(v0, v1));
            ml1 = fmaxf(ml1, fmaxf(v2, v3));
        }
        ml0 = fmaxf(ml0, __shfl_xor_sync(0xffffffffu, ml0, 1));
        ml0 = fmaxf(ml0, __shfl_xor_sync(0xffffffffu, ml0, 2));
        ml1 = fmaxf(ml1, __shfl_xor_sync(0xffffffffu, ml1, 1));
        ml1 = fmaxf(ml1, __shfl_xor_sync(0xffffffffu, ml1, 2));
        const float mn0 = fmaxf(sm0, ml0), mn1 = fmaxf(sm1, ml1);
        const float cf0 = __expf(sm0 - mn0), cf1 = __expf(sm1 - mn1);
        sm0 = mn0; sm1 = mn1;

        float rs0 = 0.0f, rs1 = 0.0f;
#pragma unroll
        for (int j = 0; j < 8; j++) {
            sacc[j][0] = __expf(sacc[j][0] - mn0);
            sacc[j][1] = __expf(sacc[j][1] - mn0);
            sacc[j][2] = __expf(sacc[j][2] - mn1);
            sacc[j][3] = __expf(sacc[j][3] - mn1);
            rs0 += sacc[j][0] + sacc[j][1];
            rs1 += sacc[j][2] + sacc[j][3];
        }
        rs0 += __shfl_xor_sync(0xffffffffu, rs0, 1);
        rs0 += __shfl_xor_sync(0xffffffffu, rs0, 2);
        rs1 += __shfl_xor_sync(0xffffffffu, rs1, 1);
        rs1 += __shfl_xor_sync(0xffffffffu, rs1, 2);
        sl0 = sl0 * cf0 + rs0;
        sl1 = sl1 * cf1 + rs1;

#pragma unroll
        for (int j = 0; j < 8; j++) {
            o[j][0] *= cf0; o[j][1] *= cf0;
            o[j][2] *= cf1; o[j][3] *= cf1;
        }

        uint32_t ph[4][4];
#pragma unroll
        for (int t = 0; t < 4; t++) {
            ph[t][0] = pack2(sacc[2 * t][0],     sacc[2 * t][1]);
            ph[t][1] = pack2(sacc[2 * t][2],     sacc[2 * t][3]);
            ph[t][2] = pack2(sacc[2 * t + 1][0], sacc[2 * t + 1][1]);
            ph[t][3] = pack2(sacc[2 * t + 1][2], sacc[2 * t + 1][3]);
        }

#pragma unroll
        for (int t = 0; t < 4; t++) {
#pragma unroll
            for (int p = 0; p < 4; p++) {
                uint32_t vh[4];
                ldsm4t(vh, stage + 8192 + swa(t * 16 + vrow, p * 2 + vch));
#pragma unroll
                for (int jj = 0; jj < 2; jj++)
                    mma16816(o[p * 2 + jj], ph[t], vh[jj * 2], vh[jj * 2 + 1]);
            }
        }

        __syncthreads();
        if (kt + 2 <= ktmax) load_kv(kt + 2);
    }

    const float inv0 = 1.0f / sl0, inv1 = 1.0f / sl1;
    const size_t row0 = (size_t)(tok0 + q0 + r0) * CD + h * HD;
    const size_t row1 = (size_t)(tok0 + q0 + r1) * CD + h * HD;
#pragma unroll
    for (int j = 0; j < 8; j++) {
        const int c0 = j * 8 + (l & 3) * 2;
        *(uint32_t*)&yh[row0 + c0] = pack2(o[j][0] * inv0, o[j][1] * inv0);
        *(uint32_t*)&yh[row1 + c0] = pack2(o[j][2] * inv1, o[j][3] * inv1);
    }
}

// ---------------------------------------------------------------------------
extern "C" void kernel_launch(void* const* d_in, const int* in_sizes, int n_in,
                              void* d_out, int out_size)
{
    const float* x      = (const float*)d_in[0];
    const float* w_attn = (const float*)d_in[1];
    const float* w_proj = (const float*)d_in[2];
    const float* b_proj = (const float*)d_in[3];
    float* out = (float*)d_out;

    __half *xh, *wah, *wph, *qkvh, *yh;
    cudaGetSymbolAddress((void**)&xh,   g_xh);
    cudaGetSymbolAddress((void**)&wah,  g_wah);
    cudaGetSymbolAddress((void**)&wph,  g_wph);
    cudaGetSymbolAddress((void**)&qkvh, g_qkvh);
    cudaGetSymbolAddress((void**)&yh,   g_yh);

    cudaFuncSetAttribute(attn_kernel,
                         cudaFuncAttributeMaxDynamicSharedMemorySize, ATT_SMEM);
    cudaFuncSetAttribute(gemm_f16<false, true>,
                         cudaFuncAttributeMaxDynamicSharedMemorySize, GEMM_SMEM);
    cudaFuncSetAttribute(gemm_f16<true, false>,
                         cudaFuncAttributeMaxDynamicSharedMemorySize, GEMM_SMEM);

    // 0) convert inputs to fp16
    cvt_f16<<<(MTOK * CD / 4 + 255) / 256, 256>>>(x, xh, MTOK * CD);
    cvt_f16<<<(NQKV * CD / 4 + 255) / 256, 256>>>(w_attn, wah, NQKV * CD);
    cvt_f16<<<(CD * CD / 4 + 255) / 256, 256>>>(w_proj, wph, CD * CD);

    // 1) QKV projection -> qkv fp16
    gemm_f16<false, true><<<dim3(NQKV / 128, MTOK / 128), 128, GEMM_SMEM>>>(
        xh, wah, nullptr, nullptr, qkvh, MTOK, NQKV, CD);

    // 2) tensor-core causal flash attention -> y fp16
    attn_kernel<<<dim3(SEQ / 128, NH, BATCH), 256, ATT_SMEM>>>(qkvh, yh);

    // 3) output projection: out = y @ w_proj^T + b_proj (fp32 out)
    gemm_f16<true, false><<<dim3(CD / 128, MTOK / 128), 128, GEMM_SMEM>>>(
        yh, wph, b_proj, out, nullptr, MTOK, CD, CD);
}

// round 11
// speedup vs baseline: 5.4095x; 1.0408x over previous
#include <cuda_runtime.h>
#include <cuda_fp16.h>
#include <cstdint>

// Problem constants
#define BATCH 8
#define SEQ   1024
#define CD    1024
#define NH    16
#define HD    64
#define MTOK  (BATCH * SEQ)      // 8192 tokens
#define NQKV  (3 * CD)           // 3072

// Scratch (no allocations allowed -> __device__ globals)
__device__ __half g_xh[MTOK * CD];
__device__ __half g_wah[NQKV * CD];
__device__ __half g_wph[CD * CD];
__device__ __half g_qkvh[MTOK * NQKV];
__device__ __half g_yh[MTOK * CD];

// ---------------------------------------------------------------------------
// PTX helpers (portable sm_80+ tensor path: cp.async + ldmatrix + mma.sync)
// ---------------------------------------------------------------------------
__device__ __forceinline__ uint32_t smem_u32(const void* p) {
    return (uint32_t)__cvta_generic_to_shared(p);
}
__device__ __forceinline__ void cp16(uint32_t dst_smem, const void* src) {
    asm volatile("cp.async.cg.shared.global [%0], [%1], 16;"
                 :: "r"(dst_smem), "l"(__cvta_generic_to_global(src)) : "memory");
}
__device__ __forceinline__ void ldsm4(uint32_t* r, uint32_t addr) {
    asm volatile("ldmatrix.sync.aligned.m8n8.x4.shared.b16 {%0,%1,%2,%3}, [%4];"
                 : "=r"(r[0]), "=r"(r[1]), "=r"(r[2]), "=r"(r[3]) : "r"(addr));
}
__device__ __forceinline__ void ldsm4t(uint32_t* r, uint32_t addr) {
    asm volatile("ldmatrix.sync.aligned.m8n8.x4.trans.shared.b16 {%0,%1,%2,%3}, [%4];"
                 : "=r"(r[0]), "=r"(r[1]), "=r"(r[2]), "=r"(r[3]) : "r"(addr));
}
__device__ __forceinline__ void mma16816(float* d, const uint32_t* a,
                                         uint32_t b0, uint32_t b1) {
    asm volatile(
        "mma.sync.aligned.m16n8k16.row.col.f32.f16.f16.f32 "
        "{%0,%1,%2,%3}, {%4,%5,%6,%7}, {%8,%9}, {%0,%1,%2,%3};"
        : "+f"(d[0]), "+f"(d[1]), "+f"(d[2]), "+f"(d[3])
        : "r"(a[0]), "r"(a[1]), "r"(a[2]), "r"(a[3]), "r"(b0), "r"(b1));
}
__device__ __forceinline__ uint32_t pack2(float a, float b) {
    __half2 h = __floats2half2_rn(a, b);
    return *(uint32_t*)&h;
}

// 128B-row swizzle: 16B chunk ch (0..7) of row r
__device__ __forceinline__ uint32_t swa(uint32_t r, uint32_t ch) {
    return r * 128u + (((ch) ^ (r & 7u)) << 4);
}

// ---------------------------------------------------------------------------
// fused fp32 -> fp16 convert for 3 tensors in one launch
// ---------------------------------------------------------------------------
__global__ __launch_bounds__(256)
void cvt3_f16(const float* __restrict__ a, __half* __restrict__ ah, int na,
              const float* __restrict__ b, __half* __restrict__ bh, int nb,
              const float* __restrict__ c, __half* __restrict__ ch, int nc)
{
    int i = (blockIdx.x * blockDim.x + threadIdx.x) * 4;
    const float* src;
    __half* dst;
    if (i < na)            { src = a + i;            dst = ah + i; }
    else if (i < na + nb)  { src = b + (i - na);     dst = bh + (i - na); }
    else if (i < na + nb + nc) { src = c + (i - na - nb); dst = ch + (i - na - nb); }
    else return;
    float4 v = *(const float4*)src;
    *(uint32_t*)dst       = pack2(v.x, v.y);
    *(uint32_t*)(dst + 2) = pack2(v.z, v.w);
}

// ---------------------------------------------------------------------------
// fp16 mma.sync GEMM: C[m,n] = sum_k A[m,k] * B[n,k]  (+bias)
// 128x256 CTA tile, 8 warps, each 64x64 (HMMA:LDSM ratio 4.0), BK=64,
// 3-stage cp.async pipe, 1 CTA/SM, 2 warps per SMSP to cover stalls.
// ---------------------------------------------------------------------------
#define A_ST   16384                    // 128 rows x 128B
#define B_ST   32768                    // 256 rows x 128B
#define STAGE_BYTES (A_ST + B_ST)       // 48 KB
#define NSTAGE 3
#define GEMM_SMEM (NSTAGE * STAGE_BYTES)  // 144 KB

template <bool BIAS, bool OUTH>
__global__ __launch_bounds__(256, 1)
void gemm_f16(const __half* __restrict__ A, const __half* __restrict__ B,
              const float* __restrict__ bias, float* __restrict__ C,
              __half* __restrict__ Ch, int M, int N, int K)
{
    extern __shared__ char smem[];
    const uint32_t sb = smem_u32(smem);
    const int tid = threadIdx.x;
    const int wid = tid >> 5, l = tid & 31;
    const int m0 = blockIdx.y * 128, n0 = blockIdx.x * 256;
    const int NCH = K >> 6;            // BK=64

    // loader: A = 128 rows, 2 thr/row (4 cp16 each); B = 256 rows, 1 thr/row
    const int alr = tid >> 1, alc = (tid & 1) * 4;
    const __half* agp = A + (size_t)(m0 + alr) * K + alc * 8;
    const __half* bgp = B + (size_t)(n0 + tid) * K;

    auto load_chunk = [&](int c) {
        const uint32_t stage = sb + (uint32_t)(c % NSTAGE) * STAGE_BYTES;
        const int k0 = c << 6;
#pragma unroll
        for (int ch = 0; ch < 4; ch++)
            cp16(stage + swa(alr, alc + ch), agp + k0 + ch * 8);
#pragma unroll
        for (int ch = 0; ch < 8; ch++)
            cp16(stage + A_ST + swa(tid, ch), bgp + k0 + ch * 8);
        asm volatile("cp.async.commit_group;" ::: "memory");
    };

    // warp tile 64x64: wm in {0,1} (m), wn in {0..3} (n)
    const int wm = wid & 1, wn = wid >> 1;

    const uint32_t arow = wm * 64 + (l & 15);
    const uint32_t ach  = l >> 4;
    const uint32_t brow = wn * 64 + (l & 7) + ((l >> 4) << 3);
    const uint32_t bch  = (l >> 3) & 1;

    float acc[4][8][4];
#pragma unroll
    for (int i = 0; i < 4; i++)
#pragma unroll
        for (int j = 0; j < 8; j++)
#pragma unroll
            for (int q = 0; q < 4; q++) acc[i][j][q] = 0.0f;

    load_chunk(0);
    load_chunk(1);

    for (int c = 0; c < NCH; c++) {
        if (c + 2 < NCH) {
            load_chunk(c + 2);
            asm volatile("cp.async.wait_group 2;" ::: "memory");
        } else if (c + 1 < NCH) {
            asm volatile("cp.async.wait_group 1;" ::: "memory");
        } else {
            asm volatile("cp.async.wait_group 0;" ::: "memory");
        }
        __syncthreads();

        const uint32_t stage = sb + (uint32_t)(c % NSTAGE) * STAGE_BYTES;
#pragma unroll
        for (int s = 0; s < 4; s++) {
            uint32_t ah[4][4];
#pragma unroll
            for (int i = 0; i < 4; i++)
                ldsm4(ah[i], stage + swa(arow + i * 16, s * 2 + ach));
            uint32_t bf[4][4];
#pragma unroll
            for (int p = 0; p < 4; p++)
                ldsm4(bf[p], stage + A_ST + swa(brow + p * 16, s * 2 + bch));
#pragma unroll
            for (int i = 0; i < 4; i++)
#pragma unroll
                for (int j = 0; j < 8; j++) {
                    const int p = j >> 1, hh = (j & 1) * 2;
                    mma16816(acc[i][j], ah[i], bf[p][hh], bf[p][hh + 1]);
                }
        }
        __syncthreads();
    }

    const int rowq = l >> 2, colq = (l & 3) * 2;
#pragma unroll
    for (int j = 0; j < 8; j++) {
        const int ccol = n0 + wn * 64 + j * 8 + colq;
        float b0 = 0.f, b1 = 0.f;
        if (BIAS) { b0 = bias[ccol]; b1 = bias[ccol + 1]; }
#pragma unroll
        for (int i = 0; i < 4; i++) {
            const int r = m0 + wm * 64 + i * 16 + rowq;
            if (OUTH) {
                *(uint32_t*)&Ch[(size_t)r * N + ccol] =
                    pack2(acc[i][j][0], acc[i][j][1]);
                *(uint32_t*)&Ch[(size_t)(r + 8) * N + ccol] =
                    pack2(acc[i][j][2], acc[i][j][3]);
            } else {
                float2 v0 = make_float2(acc[i][j][0] + b0, acc[i][j][1] + b1);
                float2 v1 = make_float2(acc[i][j][2] + b0, acc[i][j][3] + b1);
                *(float2*)&C[(size_t)r * N + ccol]       = v0;
                *(float2*)&C[(size_t)(r + 8) * N + ccol] = v1;
            }
        }
    }
}

// ---------------------------------------------------------------------------
// Tensor-core flash attention (fp16, fp32 softmax), causal. (unchanged)
// CTA = (qtile 128 rows, head, batch), 8 warps (256 thr); warp owns 16 q rows.
// KV tiles of 64 rows, 2-stage cp.async ring.
// smem: Q (16KB) + 2 stages of [K|V] (16KB each) = 48KB.
// ---------------------------------------------------------------------------
#define ATT_SMEM (16384 + 2 * 16384)

__global__ __launch_bounds__(256)
void attn_kernel(const __half* __restrict__ qkvh,
                 __half* __restrict__ yh)
{
    extern __shared__ char smem[];
    const uint32_t sb = smem_u32(smem);
    const int tid = threadIdx.x;
    const int w = tid >> 5, l = tid & 31;
    const int qt = blockIdx.x, h = blockIdx.y, b = blockIdx.z;
    const int q0 = qt * 128;
    const int ktmax = 2 * qt + 1;
    const int tok0 = b * SEQ;
    const int koff = h * HD, qoff = CD + h * HD, voff = 2 * CD + h * HD;

    const int qlr = tid >> 1, qlc = (tid & 1) * 4;
    const int klr = tid >> 2, klc = (tid & 3) * 2;

    auto load_kv = [&](int kt) {
        const int k0 = kt * 64;
        const uint32_t base = sb + 16384 + (uint32_t)(kt & 1) * 16384;
        const size_t rowoff = (size_t)(tok0 + k0 + klr) * NQKV;
        const __half* s0 = qkvh + rowoff + koff + klc * 8;
        const __half* s1 = qkvh + rowoff + voff + klc * 8;
#pragma unroll
        for (int c = 0; c < 2; c++) {
            const uint32_t o = swa(klr, klc + c);
            cp16(base + o,        s0 + c * 8);
            cp16(base + 8192 + o, s1 + c * 8);
        }
        asm volatile("cp.async.commit_group;" ::: "memory");
    };

    {
        const size_t rowoff = (size_t)(tok0 + q0 + qlr) * NQKV;
        const __half* s0 = qkvh + rowoff + qoff + qlc * 8;
#pragma unroll
        for (int c = 0; c < 4; c++)
            cp16(sb + swa(qlr, qlc + c), s0 + c * 8);
    }
    load_kv(0);
    load_kv(1);

    const uint32_t qrow = w * 16 + (l & 15);
    const uint32_t qch  = l >> 4;
    const uint32_t krow = (l & 7) + ((l >> 4) << 3);
    const uint32_t kch  = (l >> 3) & 1;
    const uint32_t vrow = (l & 7) + (((l >> 3) & 1) << 3);
    const uint32_t vch  = l >> 4;

    uint32_t qh[4][4];
    float o[8][4];
#pragma unroll
    for (int j = 0; j < 8; j++)
#pragma unroll
        for (int q = 0; q < 4; q++) o[j][q] = 0.0f;
    float sm0 = -1e30f, sm1 = -1e30f, sl0 = 0.0f, sl1 = 0.0f;

    const int r0 = w * 16 + (l >> 2);
    const int r1 = r0 + 8;
    const float scale = 0.125f;

    for (int kt = 0; kt <= ktmax; kt++) {
        if (kt < ktmax) asm volatile("cp.async.wait_group 1;" ::: "memory");
        else            asm volatile("cp.async.wait_group 0;" ::: "memory");
        __syncthreads();

        if (kt == 0) {
#pragma unroll
            for (int s = 0; s < 4; s++)
                ldsm4(qh[s], sb + swa(qrow, s * 2 + qch));
        }

        const uint32_t stage = sb + 16384 + (uint32_t)(kt & 1) * 16384;

        float sacc[8][4];
#pragma unroll
        for (int j = 0; j < 8; j++)
#pragma unroll
            for (int q = 0; q < 4; q++) sacc[j][q] = 0.0f;

#pragma unroll
        for (int s = 0; s < 4; s++) {
#pragma unroll
            for (int p = 0; p < 4; p++) {
                uint32_t kh[4];
                ldsm4(kh, stage + swa(p * 16 + krow, s * 2 + kch));
#pragma unroll
                for (int jj = 0; jj < 2; jj++)
                    mma16816(sacc[p * 2 + jj], qh[s], kh[jj * 2], kh[jj * 2 + 1]);
            }
        }

        const bool mt = (kt >= 2 * qt);
        const int rel = (kt - 2 * qt) * 64;
        float ml0 = -1e30f, ml1 = -1e30f;
#pragma unroll
        for (int j = 0; j < 8; j++) {
            const int c0 = j * 8 + (l & 3) * 2;
            float v0 = sacc[j][0] * scale, v1 = sacc[j][1] * scale;
            float v2 = sacc[j][2] * scale, v3 = sacc[j][3] * scale;
            if (mt) {
                if (rel + c0     > r0) v0 = -1e30f;
                if (rel + c0 + 1 > r0) v1 = -1e30f;
                if (rel + c0     > r1) v2 = -1e30f;
                if (rel + c0 + 1 > r1) v3 = -1e30f;
            }
            sacc[j][0] = v0; sacc[j][1] = v1; sacc[j][2] = v2; sacc[j][3] = v3;
            ml0 = fmaxf(ml0, fmaxf(v0, v1));
            ml1 = fmaxf(ml1, fmaxf(v2, v3));
        }
        ml0 = fmaxf(ml0, __shfl_xor_sync(0xffffffffu, ml0, 1));
        ml0 = fmaxf(ml0, __shfl_xor_sync(0xffffffffu, ml0, 2));
        ml1 = fmaxf(ml1, __shfl_xor_sync(0xffffffffu, ml1, 1));
        ml1 = fmaxf(ml1, __shfl_xor_sync(0xffffffffu, ml1, 2));
        const float mn0 = fmaxf(sm0, ml0), mn1 = fmaxf(sm1, ml1);
        const float cf0 = __expf(sm0 - mn0), cf1 = __expf(sm1 - mn1);
        sm0 = mn0; sm1 = mn1;

        float rs0 = 0.0f, rs1 = 0.0f;
#pragma unroll
        for (int j = 0; j < 8; j++) {
            sacc[j][0] = __expf(sacc[j][0] - mn0);
            sacc[j][1] = __expf(sacc[j][1] - mn0);
            sacc[j][2] = __expf(sacc[j][2] - mn1);
            sacc[j][3] = __expf(sacc[j][3] - mn1);
            rs0 += sacc[j][0] + sacc[j][1];
            rs1 += sacc[j][2] + sacc[j][3];
        }
        rs0 += __shfl_xor_sync(0xffffffffu, rs0, 1);
        rs0 += __shfl_xor_sync(0xffffffffu, rs0, 2);
        rs1 += __shfl_xor_sync(0xffffffffu, rs1, 1);
        rs1 += __shfl_xor_sync(0xffffffffu, rs1, 2);
        sl0 = sl0 * cf0 + rs0;
        sl1 = sl1 * cf1 + rs1;

#pragma unroll
        for (int j = 0; j < 8; j++) {
            o[j][0] *= cf0; o[j][1] *= cf0;
            o[j][2] *= cf1; o[j][3] *= cf1;
        }

        uint32_t ph[4][4];
#pragma unroll
        for (int t = 0; t < 4; t++) {
            ph[t][0] = pack2(sacc[2 * t][0],     sacc[2 * t][1]);
            ph[t][1] = pack2(sacc[2 * t][2],     sacc[2 * t][3]);
            ph[t][2] = pack2(sacc[2 * t + 1][0], sacc[2 * t + 1][1]);
            ph[t][3] = pack2(sacc[2 * t + 1][2], sacc[2 * t + 1][3]);
        }

#pragma unroll
        for (int t = 0; t < 4; t++) {
#pragma unroll
            for (int p = 0; p < 4; p++) {
                uint32_t vh[4];
                ldsm4t(vh, stage + 8192 + swa(t * 16 + vrow, p * 2 + vch));
#pragma unroll
                for (int jj = 0; jj < 2; jj++)
                    mma16816(o[p * 2 + jj], ph[t], vh[jj * 2], vh[jj * 2 + 1]);
            }
        }

        __syncthreads();
        if (kt + 2 <= ktmax) load_kv(kt + 2);
    }

    const float inv0 = 1.0f / sl0, inv1 = 1.0f / sl1;
    const size_t row0 = (size_t)(tok0 + q0 + r0) * CD + h * HD;
    const size_t row1 = (size_t)(tok0 + q0 + r1) * CD + h * HD;
#pragma unroll
    for (int j = 0; j < 8; j++) {
        const int c0 = j * 8 + (l & 3) * 2;
        *(uint32_t*)&yh[row0 + c0] = pack2(o[j][0] * inv0, o[j][1] * inv0);
        *(uint32_t*)&yh[row1 + c0] = pack2(o[j][2] * inv1, o[j][3] * inv1);
    }
}

// ---------------------------------------------------------------------------
extern "C" void kernel_launch(void* const* d_in, const int* in_sizes, int n_in,
                              void* d_out, int out_size)
{
    const float* x      = (const float*)d_in[0];
    const float* w_attn = (const float*)d_in[1];
    const float* w_proj = (const float*)d_in[2];
    const float* b_proj = (const float*)d_in[3];
    float* out = (float*)d_out;

    __half *xh, *wah, *wph, *qkvh, *yh;
    cudaGetSymbolAddress((void**)&xh,   g_xh);
    cudaGetSymbolAddress((void**)&wah,  g_wah);
    cudaGetSymbolAddress((void**)&wph,  g_wph);
    cudaGetSymbolAddress((void**)&qkvh, g_qkvh);
    cudaGetSymbolAddress((void**)&yh,   g_yh);

    cudaFuncSetAttribute(attn_kernel,
                         cudaFuncAttributeMaxDynamicSharedMemorySize, ATT_SMEM);
    cudaFuncSetAttribute(gemm_f16<false, true>,
                         cudaFuncAttributeMaxDynamicSharedMemorySize, GEMM_SMEM);
    cudaFuncSetAttribute(gemm_f16<true, false>,
                         cudaFuncAttributeMaxDynamicSharedMemorySize, GEMM_SMEM);

    // 0) convert inputs to fp16 (single fused launch)
    const int na = MTOK * CD, nb = NQKV * CD, nc = CD * CD;
    cvt3_f16<<<((na + nb + nc) / 4 + 255) / 256, 256>>>(
        x, xh, na, w_attn, wah, nb, w_proj, wph, nc);

    // 1) QKV projection -> qkv fp16
    gemm_f16<false, true><<<dim3(NQKV / 256, MTOK / 128), 256, GEMM_SMEM>>>(
        xh, wah, nullptr, nullptr, qkvh, MTOK, NQKV, CD);

    // 2) tensor-core causal flash attention -> y fp16
    attn_kernel<<<dim3(SEQ / 128, NH, BATCH), 256, ATT_SMEM>>>(qkvh, yh);

    // 3) output projection: out = y @ w_proj^T + b_proj (fp32 out)
    gemm_f16<true, false><<<dim3(CD / 256, MTOK / 128), 256, GEMM_SMEM>>>(
        yh, wph, b_proj, out, nullptr, MTOK, CD, CD);
}